// round 4
// baseline (speedup 1.0000x reference)
#include <cuda_runtime.h>
#include <cuda_bf16.h>
#include <math.h>

// Problem constants (fixed by the dataset)
#define BB 8
#define SS 4096
#define DD 1024
#define MTOT (BB * SS)   // 32768

// 128 MB scratch for upd / mem_seq (recurrence runs in place)
__device__ float g_buf[(size_t)MTOT * DD];

// ---------------------------------------------------------------------------
// NT SGEMM with bias: C[M,N] = A[M,K] * B[N,K]^T + bias[N]
// A row-major (K contiguous), B row-major (K contiguous).
// Tiles: 128x128x16, 256 threads, 8x8 per-thread microtile.
// ---------------------------------------------------------------------------
#define BM 128
#define BN 128
#define BK 16
#define TM 8
#define TN 8

__global__ __launch_bounds__(256, 2)
void gemm_nt_bias(const float* __restrict__ A,
                  const float* __restrict__ B,
                  const float* __restrict__ bias,
                  float* __restrict__ C,
                  int M, int N, int K)
{
    __shared__ float As[BK][BM];
    __shared__ float Bs[BK][BN];

    const int bx = blockIdx.x;   // N tile
    const int by = blockIdx.y;   // M tile
    const int tid = threadIdx.x;

    const int tn = (tid & 15) * TN;   // col offset within tile
    const int tm = (tid >> 4) * TM;   // row offset within tile

    const float* Ab = A + (size_t)by * BM * K;
    const float* Bb = B + (size_t)bx * BN * K;

    // loader mapping: 512 float4 per operand tile, 2 per thread
    const int lrow = tid >> 2;          // 0..63
    const int lcol = (tid & 3) * 4;     // 0,4,8,12

    float acc[TM][TN];
    #pragma unroll
    for (int i = 0; i < TM; i++)
        #pragma unroll
        for (int j = 0; j < TN; j++)
            acc[i][j] = 0.0f;

    for (int k0 = 0; k0 < K; k0 += BK) {
        // load A tile (transposed into smem)
        #pragma unroll
        for (int r = 0; r < 2; r++) {
            float4 v = *(const float4*)(Ab + (size_t)(lrow + r * 64) * K + k0 + lcol);
            As[lcol + 0][lrow + r * 64] = v.x;
            As[lcol + 1][lrow + r * 64] = v.y;
            As[lcol + 2][lrow + r * 64] = v.z;
            As[lcol + 3][lrow + r * 64] = v.w;
        }
        // load B tile (transposed into smem)
        #pragma unroll
        for (int r = 0; r < 2; r++) {
            float4 v = *(const float4*)(Bb + (size_t)(lrow + r * 64) * K + k0 + lcol);
            Bs[lcol + 0][lrow + r * 64] = v.x;
            Bs[lcol + 1][lrow + r * 64] = v.y;
            Bs[lcol + 2][lrow + r * 64] = v.z;
            Bs[lcol + 3][lrow + r * 64] = v.w;
        }
        __syncthreads();

        #pragma unroll
        for (int k = 0; k < BK; k++) {
            float a[TM], b[TN];
            float4 a0 = *(const float4*)(&As[k][tm]);
            float4 a1 = *(const float4*)(&As[k][tm + 4]);
            float4 b0 = *(const float4*)(&Bs[k][tn]);
            float4 b1 = *(const float4*)(&Bs[k][tn + 4]);
            a[0]=a0.x; a[1]=a0.y; a[2]=a0.z; a[3]=a0.w;
            a[4]=a1.x; a[5]=a1.y; a[6]=a1.z; a[7]=a1.w;
            b[0]=b0.x; b[1]=b0.y; b[2]=b0.z; b[3]=b0.w;
            b[4]=b1.x; b[5]=b1.y; b[6]=b1.z; b[7]=b1.w;
            #pragma unroll
            for (int i = 0; i < TM; i++)
                #pragma unroll
                for (int j = 0; j < TN; j++)
                    acc[i][j] = fmaf(a[i], b[j], acc[i][j]);
        }
        __syncthreads();
    }

    // epilogue: add bias, store
    float bv[TN];
    #pragma unroll
    for (int j = 0; j < TN; j++)
        bv[j] = bias[bx * BN + tn + j];

    #pragma unroll
    for (int i = 0; i < TM; i++) {
        const size_t row = (size_t)(by * BM + tm + i);
        #pragma unroll
        for (int j = 0; j < TN; j += 4) {
            float4 o;
            o.x = acc[i][j + 0] + bv[j + 0];
            o.y = acc[i][j + 1] + bv[j + 1];
            o.z = acc[i][j + 2] + bv[j + 2];
            o.w = acc[i][j + 3] + bv[j + 3];
            *(float4*)(C + row * N + bx * BN + tn + j) = o;
        }
    }
}

// ---------------------------------------------------------------------------
// Mask-gated recurrence, in place over g_buf:
//   a_t = m*decay + (1-m);  b_t = m*upd_t;  mem_t = a_t*mem_{t-1} + b_t
// One thread per (b, d) chain: 8192 threads. Unrolled by 8 so the loads of
// the next group are batched (independent of the serial FMA chain).
// ---------------------------------------------------------------------------
__global__ void recurrence_kernel(float* __restrict__ buf,
                                  const float* __restrict__ mask,
                                  const float* __restrict__ decay_p)
{
    const int g = blockIdx.x * blockDim.x + threadIdx.x;   // 0..8191
    const int b = g >> 10;
    const int d = g & (DD - 1);

    const float decay = 1.0f / (1.0f + expf(-decay_p[0]));

    const float* mrow = mask + (size_t)b * SS;
    float* p = buf + (size_t)b * SS * DD + d;

    float carry = 0.0f;
    for (int s = 0; s < SS; s += 8) {
        float u[8], mm[8];
        #pragma unroll
        for (int i = 0; i < 8; i++) {
            u[i]  = p[(size_t)(s + i) * DD];
            mm[i] = mrow[s + i];
        }
        #pragma unroll
        for (int i = 0; i < 8; i++) {
            const float a = mm[i] * decay + (1.0f - mm[i]);
            carry = fmaf(a, carry, mm[i] * u[i]);
            p[(size_t)(s + i) * DD] = carry;
        }
    }
}

// ---------------------------------------------------------------------------
// kernel_launch
// Inputs: 0:x (B,S,D)  1:mask (B,S)  2:Wu (D,D)  3:bu (D)
//         4:Wf (D,D)   5:bf (D)      6:decay_param (1)
// Output: (B,S,D) float32
// ---------------------------------------------------------------------------
extern "C" void kernel_launch(void* const* d_in, const int* in_sizes, int n_in,
                              void* d_out, int out_size)
{
    const float* x     = (const float*)d_in[0];
    const float* mask  = (const float*)d_in[1];
    const float* Wu    = (const float*)d_in[2];
    const float* bu    = (const float*)d_in[3];
    const float* Wf    = (const float*)d_in[4];
    const float* bf    = (const float*)d_in[5];
    const float* decay = (const float*)d_in[6];
    float* out = (float*)d_out;

    float* buf = nullptr;
    cudaGetSymbolAddress((void**)&buf, g_buf);

    dim3 grid(DD / BN, MTOT / BM);   // (8, 256)

    // 1) upd = x*Wu^T + bu
    gemm_nt_bias<<<grid, 256>>>(x, Wu, bu, buf, MTOT, DD, DD);

    // 2) in-place masked recurrence over S
    recurrence_kernel<<<BB * DD / 64, 64>>>(buf, mask, decay);

    // 3) out = mem*Wf^T + bf
    gemm_nt_bias<<<grid, 256>>>(buf, Wf, bf, out, MTOT, DD, DD);
}

// round 8
// speedup vs baseline: 1.8408x; 1.8408x over previous
#include <cuda_runtime.h>
#include <cuda_bf16.h>
#include <math.h>
#include <stdint.h>

// Problem constants (fixed by the dataset)
#define BB 8
#define SS 4096
#define DD 1024
#define MTOT (BB * SS)   // 32768

// ---------------------------------------------------------------------------
// Scratch (device globals; no allocation allowed)
// ---------------------------------------------------------------------------
__device__ float          g_upd[(size_t)MTOT * DD];   // GEMM1 output (fp32)
__device__ __nv_bfloat16  g_xhi[(size_t)MTOT * DD];
__device__ __nv_bfloat16  g_xlo[(size_t)MTOT * DD];
__device__ __nv_bfloat16  g_mhi[(size_t)MTOT * DD];
__device__ __nv_bfloat16  g_mlo[(size_t)MTOT * DD];
__device__ __nv_bfloat16  g_wuhi[DD * DD];
__device__ __nv_bfloat16  g_wulo[DD * DD];
__device__ __nv_bfloat16  g_wfhi[DD * DD];
__device__ __nv_bfloat16  g_wflo[DD * DD];

// ---------------------------------------------------------------------------
// PTX helpers (base-target only: cp.async / ldmatrix / mma.sync — no tcgen05,
// which requires the sm_103a '.a' target the harness's nvcc does not emit)
// ---------------------------------------------------------------------------
__device__ __forceinline__ uint32_t smem_u32(const void* p) {
    uint32_t a;
    asm("{ .reg .u64 t; cvta.to.shared.u64 t, %1; cvt.u32.u64 %0, t; }" : "=r"(a) : "l"(p));
    return a;
}
__device__ __forceinline__ void cp16(uint32_t dst, const void* src) {
    asm volatile("cp.async.cg.shared.global [%0], [%1], 16;" :: "r"(dst), "l"(src));
}
__device__ __forceinline__ void cp_commit() {
    asm volatile("cp.async.commit_group;" ::: "memory");
}
template<int N>
__device__ __forceinline__ void cp_wait() {
    asm volatile("cp.async.wait_group %0;" :: "n"(N) : "memory");
}
__device__ __forceinline__ void ldm_x4(uint32_t* r, uint32_t addr) {
    asm volatile("ldmatrix.sync.aligned.m8n8.x4.shared.b16 {%0,%1,%2,%3}, [%4];"
                 : "=r"(r[0]), "=r"(r[1]), "=r"(r[2]), "=r"(r[3]) : "r"(addr));
}
__device__ __forceinline__ void mma16816(float* d, const uint32_t* a, const uint32_t* b) {
    asm volatile(
        "mma.sync.aligned.m16n8k16.row.col.f32.bf16.bf16.f32 "
        "{%0,%1,%2,%3}, {%4,%5,%6,%7}, {%8,%9}, {%0,%1,%2,%3};"
        : "+f"(d[0]), "+f"(d[1]), "+f"(d[2]), "+f"(d[3])
        : "r"(a[0]), "r"(a[1]), "r"(a[2]), "r"(a[3]), "r"(b[0]), "r"(b[1]));
}

// ---------------------------------------------------------------------------
// Split-bf16 GEMM: C[M,N] = sum_p Ap[M,K]*Bp[N,K]^T + bias[N], fp32 accum.
// Products: (hi,hi), (hi,lo), (lo,hi)  == effective K of 3*1024.
// CTA tile 128x128, BK=32, 8 warps (4x2), warp tile 32x64. cp.async double buf.
// ---------------------------------------------------------------------------
#define BM 128
#define BN 128
#define BKK 32
#define APAD 8
#define ASTR (BKK + APAD)     // 40 bf16 per row (80 B) -> conflict-free ldmatrix
#define NITER (3 * DD / BKK)  // 96

__global__ __launch_bounds__(256, 2)
void gemm_mma_split(const __nv_bfloat16* __restrict__ Ahi,
                    const __nv_bfloat16* __restrict__ Alo,
                    const __nv_bfloat16* __restrict__ Bhi,
                    const __nv_bfloat16* __restrict__ Blo,
                    const float* __restrict__ bias,
                    float* __restrict__ C)
{
    __shared__ __nv_bfloat16 As[2][BM][ASTR];
    __shared__ __nv_bfloat16 Bs[2][BN][ASTR];

    const int tid  = threadIdx.x;
    const int wid  = tid >> 5;
    const int lane = tid & 31;
    const int wm   = wid & 3;    // warp row (M): 0..3
    const int wn   = wid >> 2;   // warp col (N): 0..1
    const int bx   = blockIdx.x; // N tile
    const int by   = blockIdx.y; // M tile

    // global loader mapping: per tile 512 x 16B chunks; this thread owns
    // chunks tid and tid+256 -> rows lr0, lr0+64, bf16-col lc
    const int lr0 = tid >> 2;
    const int lc  = (tid & 3) * 8;

    // per-product base pointers for this thread's load slice (hoisted)
    const __nv_bfloat16* Abase[3];
    const __nv_bfloat16* Bbase[3];
    {
        const size_t aoff = (size_t)(by * BM + lr0) * DD + lc;
        const size_t boff = (size_t)(bx * BN + lr0) * DD + lc;
        Abase[0] = Ahi + aoff;  Bbase[0] = Bhi + boff;
        Abase[1] = Ahi + aoff;  Bbase[1] = Blo + boff;
        Abase[2] = Alo + aoff;  Bbase[2] = Bhi + boff;
    }

    // ldmatrix source addressing
    // A tiles per x4: (m0..7,k0..7),(m8..15,k0..7),(m0..7,k8..15),(m8..15,k8..15)
    const int a_row = (lane & 7) + ((lane >> 3) & 1) * 8;
    const int a_col = (lane >> 4) * 8;
    // B tiles per x4: (n0..7,k0..7),(n0..7,k8..15),(n8..15,k0..7),(n8..15,k8..15)
    const int b_row = (lane & 7) + (lane >> 4) * 8;
    const int b_col = ((lane >> 3) & 1) * 8;

    const uint32_t sA = smem_u32(&As[0][0][0]);
    const uint32_t sB = smem_u32(&Bs[0][0][0]);
    const uint32_t stageA_bytes = BM * ASTR * 2;
    const uint32_t stageB_bytes = BN * ASTR * 2;

    float acc[2][8][4];
    #pragma unroll
    for (int i = 0; i < 2; i++)
        #pragma unroll
        for (int j = 0; j < 8; j++)
            #pragma unroll
            for (int q = 0; q < 4; q++)
                acc[i][j][q] = 0.0f;

    // ---- issue loads for iteration `it` into stage `st` ----
    auto issue = [&](int it, int st) {
        const int p  = it >> 5;          // product pair
        const int kc = (it & 31) * BKK;  // k offset within pair
        const __nv_bfloat16* Ag = Abase[p] + kc;
        const __nv_bfloat16* Bg = Bbase[p] + kc;
        #pragma unroll
        for (int j = 0; j < 2; j++) {
            const size_t roff = (size_t)j * 64 * DD;
            const uint32_t soff = (uint32_t)(j * 64 * ASTR * 2);
            cp16(sA + st * stageA_bytes + (lr0 * ASTR + lc) * 2 + soff, Ag + roff);
            cp16(sB + st * stageB_bytes + (lr0 * ASTR + lc) * 2 + soff, Bg + roff);
        }
        cp_commit();
    };

    issue(0, 0);

    for (int it = 0; it < NITER; it++) {
        const int st = it & 1;
        if (it + 1 < NITER) {
            issue(it + 1, st ^ 1);
            cp_wait<1>();
        } else {
            cp_wait<0>();
        }
        __syncthreads();

        const uint32_t stA = sA + st * stageA_bytes;
        const uint32_t stB = sB + st * stageB_bytes;

        #pragma unroll
        for (int ks = 0; ks < 2; ks++) {
            uint32_t afr[2][4];
            #pragma unroll
            for (int mt = 0; mt < 2; mt++) {
                const int row = wm * 32 + mt * 16 + a_row;
                ldm_x4(afr[mt], stA + (row * ASTR + ks * 16 + a_col) * 2);
            }
            uint32_t bfr[4][4];   // 4 n16-groups; [g][0..1] = n-even frag, [g][2..3] = n-odd frag
            #pragma unroll
            for (int g = 0; g < 4; g++) {
                const int row = wn * 64 + g * 16 + b_row;
                ldm_x4(bfr[g], stB + (row * ASTR + ks * 16 + b_col) * 2);
            }
            #pragma unroll
            for (int mt = 0; mt < 2; mt++)
                #pragma unroll
                for (int g = 0; g < 4; g++) {
                    mma16816(acc[mt][2 * g + 0], afr[mt], &bfr[g][0]);
                    mma16816(acc[mt][2 * g + 1], afr[mt], &bfr[g][2]);
                }
        }
        __syncthreads();
    }

    // ---- epilogue: bias add + store (fp32) ----
    const int crow = by * BM + wm * 32 + (lane >> 2);
    const int ccol = bx * BN + wn * 64 + (lane & 3) * 2;
    #pragma unroll
    for (int mt = 0; mt < 2; mt++) {
        #pragma unroll
        for (int nt = 0; nt < 8; nt++) {
            const int gn = ccol + nt * 8;
            const float2 bv = *(const float2*)(bias + gn);
            float2 o0, o1;
            o0.x = acc[mt][nt][0] + bv.x;
            o0.y = acc[mt][nt][1] + bv.y;
            o1.x = acc[mt][nt][2] + bv.x;
            o1.y = acc[mt][nt][3] + bv.y;
            *(float2*)(C + (size_t)(crow + mt * 16) * DD + gn)     = o0;
            *(float2*)(C + (size_t)(crow + mt * 16 + 8) * DD + gn) = o1;
        }
    }
}

// ---------------------------------------------------------------------------
// fp32 -> (hi, lo) bf16 split, vectorized
// ---------------------------------------------------------------------------
__global__ void split_kernel(const float* __restrict__ in,
                             __nv_bfloat16* __restrict__ hi,
                             __nv_bfloat16* __restrict__ lo, int n4)
{
    for (int i = blockIdx.x * blockDim.x + threadIdx.x; i < n4; i += gridDim.x * blockDim.x) {
        const float4 v = ((const float4*)in)[i];
        __nv_bfloat16 hx = __float2bfloat16_rn(v.x);
        __nv_bfloat16 hy = __float2bfloat16_rn(v.y);
        __nv_bfloat16 hz = __float2bfloat16_rn(v.z);
        __nv_bfloat16 hw = __float2bfloat16_rn(v.w);
        __nv_bfloat162* h2 = (__nv_bfloat162*)hi;
        __nv_bfloat162* l2 = (__nv_bfloat162*)lo;
        h2[2 * i + 0] = __nv_bfloat162(hx, hy);
        h2[2 * i + 1] = __nv_bfloat162(hz, hw);
        l2[2 * i + 0] = __nv_bfloat162(__float2bfloat16_rn(v.x - __bfloat162float(hx)),
                                       __float2bfloat16_rn(v.y - __bfloat162float(hy)));
        l2[2 * i + 1] = __nv_bfloat162(__float2bfloat16_rn(v.z - __bfloat162float(hz)),
                                       __float2bfloat16_rn(v.w - __bfloat162float(hw)));
    }
}

// ---------------------------------------------------------------------------
// Mask-gated recurrence over S, fused with bf16 hi/lo split of the output.
// One thread per (b, d) chain.
// ---------------------------------------------------------------------------
__global__ void recurrence_split(const float* __restrict__ upd,
                                 const float* __restrict__ mask,
                                 const float* __restrict__ decay_p,
                                 __nv_bfloat16* __restrict__ mhi,
                                 __nv_bfloat16* __restrict__ mlo)
{
    const int g = blockIdx.x * blockDim.x + threadIdx.x;   // 0..8191
    const int b = g >> 10;
    const int d = g & (DD - 1);

    const float decay = 1.0f / (1.0f + expf(-decay_p[0]));

    const float* mrow = mask + (size_t)b * SS;
    const float* p = upd + (size_t)b * SS * DD + d;
    __nv_bfloat16* ph = mhi + (size_t)b * SS * DD + d;
    __nv_bfloat16* pl = mlo + (size_t)b * SS * DD + d;

    float carry = 0.0f;
    for (int s = 0; s < SS; s += 8) {
        float u[8], mm[8];
        #pragma unroll
        for (int i = 0; i < 8; i++) {
            u[i]  = p[(size_t)(s + i) * DD];
            mm[i] = mrow[s + i];
        }
        #pragma unroll
        for (int i = 0; i < 8; i++) {
            const float a = mm[i] * decay + (1.0f - mm[i]);
            carry = fmaf(a, carry, mm[i] * u[i]);
            const __nv_bfloat16 h = __float2bfloat16_rn(carry);
            ph[(size_t)(s + i) * DD] = h;
            pl[(size_t)(s + i) * DD] = __float2bfloat16_rn(carry - __bfloat162float(h));
        }
    }
}

// ---------------------------------------------------------------------------
// kernel_launch
// Inputs: 0:x (B,S,D)  1:mask (B,S)  2:Wu (D,D)  3:bu (D)
//         4:Wf (D,D)   5:bf (D)      6:decay_param (1)
// ---------------------------------------------------------------------------
extern "C" void kernel_launch(void* const* d_in, const int* in_sizes, int n_in,
                              void* d_out, int out_size)
{
    const float* x     = (const float*)d_in[0];
    const float* mask  = (const float*)d_in[1];
    const float* Wu    = (const float*)d_in[2];
    const float* bu    = (const float*)d_in[3];
    const float* Wf    = (const float*)d_in[4];
    const float* bf    = (const float*)d_in[5];
    const float* decay = (const float*)d_in[6];
    float* out = (float*)d_out;

    float *upd;  __nv_bfloat16 *xhi, *xlo, *mhi, *mlo, *wuhi, *wulo, *wfhi, *wflo;
    cudaGetSymbolAddress((void**)&upd,  g_upd);
    cudaGetSymbolAddress((void**)&xhi,  g_xhi);
    cudaGetSymbolAddress((void**)&xlo,  g_xlo);
    cudaGetSymbolAddress((void**)&mhi,  g_mhi);
    cudaGetSymbolAddress((void**)&mlo,  g_mlo);
    cudaGetSymbolAddress((void**)&wuhi, g_wuhi);
    cudaGetSymbolAddress((void**)&wulo, g_wulo);
    cudaGetSymbolAddress((void**)&wfhi, g_wfhi);
    cudaGetSymbolAddress((void**)&wflo, g_wflo);

    // splits
    split_kernel<<<2048, 256>>>(x,  xhi,  xlo,  MTOT * DD / 4);
    split_kernel<<<256, 256>>>(Wu, wuhi, wulo, DD * DD / 4);
    split_kernel<<<256, 256>>>(Wf, wfhi, wflo, DD * DD / 4);

    dim3 grid(DD / BN, MTOT / BM);   // (8, 256)

    // 1) upd = x*Wu^T + bu  (tensor cores via mma.sync, split-bf16)
    gemm_mma_split<<<grid, 256>>>(xhi, xlo, wuhi, wulo, bu, upd);

    // 2) masked recurrence, fused with hi/lo split of mem
    recurrence_split<<<BB * DD / 64, 64>>>(upd, mask, decay, mhi, mlo);

    // 3) out = mem*Wf^T + bf
    gemm_mma_split<<<grid, 256>>>(mhi, mlo, wfhi, wflo, bf, out);
}

// round 9
// speedup vs baseline: 2.8201x; 1.5320x over previous
#include <cuda_runtime.h>
#include <cuda_bf16.h>
#include <math.h>
#include <stdint.h>

// Problem constants (fixed by the dataset)
#define BB 8
#define SS 4096
#define DD 1024
#define MTOT (BB * SS)   // 32768

#define NCH 8
#define CHS (SS / NCH)   // 512 steps per chunk
#define NCD (BB * DD)    // 8192 chains

// ---------------------------------------------------------------------------
// Scratch (device globals; no allocation allowed)
// ---------------------------------------------------------------------------
__device__ float          g_upd[(size_t)MTOT * DD];   // GEMM1 output (fp32)
__device__ __nv_bfloat16  g_xhi[(size_t)MTOT * DD];
__device__ __nv_bfloat16  g_xlo[(size_t)MTOT * DD];
__device__ __nv_bfloat16  g_mhi[(size_t)MTOT * DD];
__device__ __nv_bfloat16  g_mlo[(size_t)MTOT * DD];
__device__ __nv_bfloat16  g_wuhi[DD * DD];
__device__ __nv_bfloat16  g_wulo[DD * DD];
__device__ __nv_bfloat16  g_wfhi[DD * DD];
__device__ __nv_bfloat16  g_wflo[DD * DD];
// chunked-scan summaries
__device__ float g_Ap[NCH * NCD];
__device__ float g_Be[NCH * NCD];
__device__ float g_cin[NCH * NCD];

// ---------------------------------------------------------------------------
// PTX helpers (base-target only: cp.async / ldmatrix / mma.sync — no tcgen05,
// which requires the sm_103a '.a' target the harness's nvcc does not emit)
// ---------------------------------------------------------------------------
__device__ __forceinline__ uint32_t smem_u32(const void* p) {
    uint32_t a;
    asm("{ .reg .u64 t; cvta.to.shared.u64 t, %1; cvt.u32.u64 %0, t; }" : "=r"(a) : "l"(p));
    return a;
}
__device__ __forceinline__ void cp16(uint32_t dst, const void* src) {
    asm volatile("cp.async.cg.shared.global [%0], [%1], 16;" :: "r"(dst), "l"(src));
}
__device__ __forceinline__ void cp_commit() {
    asm volatile("cp.async.commit_group;" ::: "memory");
}
template<int N>
__device__ __forceinline__ void cp_wait() {
    asm volatile("cp.async.wait_group %0;" :: "n"(N) : "memory");
}
__device__ __forceinline__ void ldm_x4(uint32_t* r, uint32_t addr) {
    asm volatile("ldmatrix.sync.aligned.m8n8.x4.shared.b16 {%0,%1,%2,%3}, [%4];"
                 : "=r"(r[0]), "=r"(r[1]), "=r"(r[2]), "=r"(r[3]) : "r"(addr));
}
__device__ __forceinline__ void mma16816(float* d, const uint32_t* a, const uint32_t* b) {
    asm volatile(
        "mma.sync.aligned.m16n8k16.row.col.f32.bf16.bf16.f32 "
        "{%0,%1,%2,%3}, {%4,%5,%6,%7}, {%8,%9}, {%0,%1,%2,%3};"
        : "+f"(d[0]), "+f"(d[1]), "+f"(d[2]), "+f"(d[3])
        : "r"(a[0]), "r"(a[1]), "r"(a[2]), "r"(a[3]), "r"(b[0]), "r"(b[1]));
}

// ---------------------------------------------------------------------------
// Split-bf16 GEMM: C = Ahi*Bhi^T + Ahi*Blo^T + Alo*Bhi^T + bias, fp32 accum.
// All 4 tiles loaded ONCE per k-block; 3 products computed from them.
// CTA tile 128x128, BK=32, 8 warps (4x2), warp tile 32x64.
// 2-stage cp.async pipeline, ONE __syncthreads per k-block.
// ---------------------------------------------------------------------------
#define BM 128
#define BN 128
#define BKK 32
#define ASTR 40                       // 32 + 8 pad bf16 -> 80B rows, conflict-free
#define TILE_B (128 * ASTR * 2)       // 10240 B per tile
#define STAGE_B (4 * TILE_B)          // 40960 B (AH, AL, BH, BL)
#define GEMM_SMEM (2 * STAGE_B)       // 81920 B
#define NKB (DD / BKK)                // 32

__global__ __launch_bounds__(256, 2)
void gemm_mma_split(const __nv_bfloat16* __restrict__ Ahi,
                    const __nv_bfloat16* __restrict__ Alo,
                    const __nv_bfloat16* __restrict__ Bhi,
                    const __nv_bfloat16* __restrict__ Blo,
                    const float* __restrict__ bias,
                    float* __restrict__ C)
{
    extern __shared__ __align__(16) char smem[];
    const uint32_t sb = smem_u32(smem);

    const int tid  = threadIdx.x;
    const int wid  = tid >> 5;
    const int lane = tid & 31;
    const int wm   = wid & 3;    // warp row (M): 0..3
    const int wn   = wid >> 2;   // warp col (N): 0..1
    const int bx   = blockIdx.x; // N tile
    const int by   = blockIdx.y; // M tile

    // loader mapping: thread owns rows r0, r0+64 at 16B-chunk c16 of each tile
    const int r0  = tid >> 2;
    const int c16 = tid & 3;
    const __nv_bfloat16* Ah0 = Ahi + (size_t)(by * BM + r0) * DD + c16 * 8;
    const __nv_bfloat16* Al0 = Alo + (size_t)(by * BM + r0) * DD + c16 * 8;
    const __nv_bfloat16* Bh0 = Bhi + (size_t)(bx * BN + r0) * DD + c16 * 8;
    const __nv_bfloat16* Bl0 = Blo + (size_t)(bx * BN + r0) * DD + c16 * 8;
    const uint32_t dstb = (uint32_t)(r0 * 80 + c16 * 16);

    // ldmatrix addressing
    const int a_row = (lane & 7) + ((lane >> 3) & 1) * 8;
    const int a_col = (lane >> 4) * 8;
    const int b_row = (lane & 7) + (lane >> 4) * 8;
    const int b_col = ((lane >> 3) & 1) * 8;

    float acc[2][8][4];
    #pragma unroll
    for (int i = 0; i < 2; i++)
        #pragma unroll
        for (int j = 0; j < 8; j++)
            #pragma unroll
            for (int q = 0; q < 4; q++)
                acc[i][j][q] = 0.0f;

    auto issue = [&](int kb, int st) {
        const uint32_t stg = sb + st * STAGE_B;
        const int ko = kb * BKK;
        #pragma unroll
        for (int j = 0; j < 2; j++) {
            const size_t ro = (size_t)j * 64 * DD;
            const uint32_t so = (uint32_t)(j * 64 * 80);
            cp16(stg + 0 * TILE_B + dstb + so, Ah0 + ro + ko);
            cp16(stg + 1 * TILE_B + dstb + so, Al0 + ro + ko);
            cp16(stg + 2 * TILE_B + dstb + so, Bh0 + ro + ko);
            cp16(stg + 3 * TILE_B + dstb + so, Bl0 + ro + ko);
        }
        cp_commit();
    };

    issue(0, 0);

    for (int kb = 0; kb < NKB; kb++) {
        const int st = kb & 1;
        cp_wait<0>();
        __syncthreads();                  // stage `st` visible; prev compute done
        if (kb + 1 < NKB) issue(kb + 1, st ^ 1);   // overlap next load w/ compute

        const uint32_t stg = sb + st * STAGE_B;
        #pragma unroll
        for (int ks = 0; ks < 2; ks++) {
            uint32_t aH[2][4], aL[2][4];
            #pragma unroll
            for (int mt = 0; mt < 2; mt++) {
                const uint32_t ra =
                    (uint32_t)(((wm * 32 + mt * 16 + a_row) * ASTR + ks * 16 + a_col) * 2);
                ldm_x4(aH[mt], stg + 0 * TILE_B + ra);
                ldm_x4(aL[mt], stg + 1 * TILE_B + ra);
            }
            #pragma unroll
            for (int g = 0; g < 4; g++) {
                const uint32_t rb =
                    (uint32_t)(((wn * 64 + g * 16 + b_row) * ASTR + ks * 16 + b_col) * 2);
                uint32_t bH[4], bL[4];
                ldm_x4(bH, stg + 2 * TILE_B + rb);
                ldm_x4(bL, stg + 3 * TILE_B + rb);
                #pragma unroll
                for (int mt = 0; mt < 2; mt++) {
                    mma16816(acc[mt][2 * g + 0], aH[mt], bH);
                    mma16816(acc[mt][2 * g + 1], aH[mt], bH + 2);
                    mma16816(acc[mt][2 * g + 0], aH[mt], bL);
                    mma16816(acc[mt][2 * g + 1], aH[mt], bL + 2);
                    mma16816(acc[mt][2 * g + 0], aL[mt], bH);
                    mma16816(acc[mt][2 * g + 1], aL[mt], bH + 2);
                }
            }
        }
    }

    // ---- epilogue: bias add + store (fp32) ----
    const int crow = by * BM + wm * 32 + (lane >> 2);
    const int ccol = bx * BN + wn * 64 + (lane & 3) * 2;
    #pragma unroll
    for (int mt = 0; mt < 2; mt++) {
        #pragma unroll
        for (int nt = 0; nt < 8; nt++) {
            const int gn = ccol + nt * 8;
            const float2 bv = *(const float2*)(bias + gn);
            float2 o0, o1;
            o0.x = acc[mt][nt][0] + bv.x;
            o0.y = acc[mt][nt][1] + bv.y;
            o1.x = acc[mt][nt][2] + bv.x;
            o1.y = acc[mt][nt][3] + bv.y;
            *(float2*)(C + (size_t)(crow + mt * 16) * DD + gn)     = o0;
            *(float2*)(C + (size_t)(crow + mt * 16 + 8) * DD + gn) = o1;
        }
    }
}

// ---------------------------------------------------------------------------
// fp32 -> (hi, lo) bf16 split, vectorized
// ---------------------------------------------------------------------------
__global__ void split_kernel(const float* __restrict__ in,
                             __nv_bfloat16* __restrict__ hi,
                             __nv_bfloat16* __restrict__ lo, int n4)
{
    for (int i = blockIdx.x * blockDim.x + threadIdx.x; i < n4; i += gridDim.x * blockDim.x) {
        const float4 v = ((const float4*)in)[i];
        __nv_bfloat16 hx = __float2bfloat16_rn(v.x);
        __nv_bfloat16 hy = __float2bfloat16_rn(v.y);
        __nv_bfloat16 hz = __float2bfloat16_rn(v.z);
        __nv_bfloat16 hw = __float2bfloat16_rn(v.w);
        __nv_bfloat162* h2 = (__nv_bfloat162*)hi;
        __nv_bfloat162* l2 = (__nv_bfloat162*)lo;
        h2[2 * i + 0] = __nv_bfloat162(hx, hy);
        h2[2 * i + 1] = __nv_bfloat162(hz, hw);
        l2[2 * i + 0] = __nv_bfloat162(__float2bfloat16_rn(v.x - __bfloat162float(hx)),
                                       __float2bfloat16_rn(v.y - __bfloat162float(hy)));
        l2[2 * i + 1] = __nv_bfloat162(__float2bfloat16_rn(v.z - __bfloat162float(hz)),
                                       __float2bfloat16_rn(v.w - __bfloat162float(hw)));
    }
}

// ---------------------------------------------------------------------------
// Chunked scan: pass1 computes per-chunk (A_prod, B_end); combine chains the
// NCH summaries per (b,d); pass2 recomputes with correct carry-in and writes
// the bf16 hi/lo split. 65536 threads in passes 1/2 (8x parallelism).
// ---------------------------------------------------------------------------
__device__ __forceinline__ float get_decay(const float* decay_p) {
    return 1.0f / (1.0f + expf(-decay_p[0]));
}

__global__ void scan_pass1(const float* __restrict__ upd,
                           const float* __restrict__ mask,
                           const float* __restrict__ decay_p,
                           float* __restrict__ Ap, float* __restrict__ Be)
{
    const int g  = blockIdx.x * blockDim.x + threadIdx.x;  // 0..65535
    const int ch = g >> 13;
    const int cd = g & (NCD - 1);
    const int b  = cd >> 10;
    const int d  = cd & (DD - 1);
    const float decay = get_decay(decay_p);

    const float* mrow = mask + (size_t)b * SS + ch * CHS;
    const float* p = upd + ((size_t)b * SS + (size_t)ch * CHS) * DD + d;

    float A = 1.0f, acc = 0.0f;
    for (int s = 0; s < CHS; s += 8) {
        float u[8], mm[8];
        #pragma unroll
        for (int i = 0; i < 8; i++) {
            u[i]  = p[(size_t)(s + i) * DD];
            mm[i] = mrow[s + i];
        }
        #pragma unroll
        for (int i = 0; i < 8; i++) {
            const float a = mm[i] * decay + (1.0f - mm[i]);
            acc = fmaf(a, acc, mm[i] * u[i]);
            A *= a;
        }
    }
    Ap[g] = A;
    Be[g] = acc;
}

__global__ void scan_combine(const float* __restrict__ Ap,
                             const float* __restrict__ Be,
                             float* __restrict__ cin)
{
    const int g = blockIdx.x * blockDim.x + threadIdx.x;   // 0..8191
    float carry = 0.0f;
    #pragma unroll
    for (int ch = 0; ch < NCH; ch++) {
        cin[ch * NCD + g] = carry;
        carry = fmaf(Ap[ch * NCD + g], carry, Be[ch * NCD + g]);
    }
}

__global__ void scan_pass2(const float* __restrict__ upd,
                           const float* __restrict__ mask,
                           const float* __restrict__ decay_p,
                           const float* __restrict__ cin,
                           __nv_bfloat16* __restrict__ mhi,
                           __nv_bfloat16* __restrict__ mlo)
{
    const int g  = blockIdx.x * blockDim.x + threadIdx.x;  // 0..65535
    const int ch = g >> 13;
    const int cd = g & (NCD - 1);
    const int b  = cd >> 10;
    const int d  = cd & (DD - 1);
    const float decay = get_decay(decay_p);

    const float* mrow = mask + (size_t)b * SS + ch * CHS;
    const size_t base = ((size_t)b * SS + (size_t)ch * CHS) * DD + d;
    const float* p = upd + base;
    __nv_bfloat16* ph = mhi + base;
    __nv_bfloat16* pl = mlo + base;

    float carry = cin[g];
    for (int s = 0; s < CHS; s += 8) {
        float u[8], mm[8];
        #pragma unroll
        for (int i = 0; i < 8; i++) {
            u[i]  = p[(size_t)(s + i) * DD];
            mm[i] = mrow[s + i];
        }
        #pragma unroll
        for (int i = 0; i < 8; i++) {
            const float a = mm[i] * decay + (1.0f - mm[i]);
            carry = fmaf(a, carry, mm[i] * u[i]);
            const __nv_bfloat16 h = __float2bfloat16_rn(carry);
            ph[(size_t)(s + i) * DD] = h;
            pl[(size_t)(s + i) * DD] = __float2bfloat16_rn(carry - __bfloat162float(h));
        }
    }
}

// ---------------------------------------------------------------------------
// kernel_launch
// Inputs: 0:x (B,S,D)  1:mask (B,S)  2:Wu (D,D)  3:bu (D)
//         4:Wf (D,D)   5:bf (D)      6:decay_param (1)
// ---------------------------------------------------------------------------
extern "C" void kernel_launch(void* const* d_in, const int* in_sizes, int n_in,
                              void* d_out, int out_size)
{
    const float* x     = (const float*)d_in[0];
    const float* mask  = (const float*)d_in[1];
    const float* Wu    = (const float*)d_in[2];
    const float* bu    = (const float*)d_in[3];
    const float* Wf    = (const float*)d_in[4];
    const float* bf    = (const float*)d_in[5];
    const float* decay = (const float*)d_in[6];
    float* out = (float*)d_out;

    float *upd, *Ap, *Be, *cin;
    __nv_bfloat16 *xhi, *xlo, *mhi, *mlo, *wuhi, *wulo, *wfhi, *wflo;
    cudaGetSymbolAddress((void**)&upd,  g_upd);
    cudaGetSymbolAddress((void**)&xhi,  g_xhi);
    cudaGetSymbolAddress((void**)&xlo,  g_xlo);
    cudaGetSymbolAddress((void**)&mhi,  g_mhi);
    cudaGetSymbolAddress((void**)&mlo,  g_mlo);
    cudaGetSymbolAddress((void**)&wuhi, g_wuhi);
    cudaGetSymbolAddress((void**)&wulo, g_wulo);
    cudaGetSymbolAddress((void**)&wfhi, g_wfhi);
    cudaGetSymbolAddress((void**)&wflo, g_wflo);
    cudaGetSymbolAddress((void**)&Ap,   g_Ap);
    cudaGetSymbolAddress((void**)&Be,   g_Be);
    cudaGetSymbolAddress((void**)&cin,  g_cin);

    cudaFuncSetAttribute(gemm_mma_split, cudaFuncAttributeMaxDynamicSharedMemorySize, GEMM_SMEM);

    // splits
    split_kernel<<<2048, 256>>>(x,  xhi,  xlo,  MTOT * DD / 4);
    split_kernel<<<256, 256>>>(Wu, wuhi, wulo, DD * DD / 4);
    split_kernel<<<256, 256>>>(Wf, wfhi, wflo, DD * DD / 4);

    dim3 grid(DD / BN, MTOT / BM);   // (8, 256)

    // 1) upd = x*Wu^T + bu  (tensor cores via mma.sync, split-bf16)
    gemm_mma_split<<<grid, 256, GEMM_SMEM>>>(xhi, xlo, wuhi, wulo, bu, upd);

    // 2) masked recurrence via chunked scan, fused with hi/lo split of mem
    scan_pass1<<<NCH * NCD / 256, 256>>>(upd, mask, decay, Ap, Be);
    scan_combine<<<NCD / 256, 256>>>(Ap, Be, cin);
    scan_pass2<<<NCH * NCD / 256, 256>>>(upd, mask, decay, cin, mhi, mlo);

    // 3) out = mem*Wf^T + bf
    gemm_mma_split<<<grid, 256, GEMM_SMEM>>>(mhi, mlo, wfhi, wflo, bf, out);
}

// round 10
// speedup vs baseline: 3.2366x; 1.1477x over previous
#include <cuda_runtime.h>
#include <cuda_bf16.h>
#include <math.h>
#include <stdint.h>

// Problem constants (fixed by the dataset)
#define BB 8
#define SS 4096
#define DD 1024
#define MTOT (BB * SS)   // 32768

#define NCH 8
#define CHS (SS / NCH)   // 512 steps per chunk
#define NCD (BB * DD)    // 8192 chains

// ---------------------------------------------------------------------------
// Scratch (device globals; no allocation allowed). Zero-initialized at load.
// ---------------------------------------------------------------------------
__device__ float          g_y[(size_t)MTOT * DD];     // y = x*W2^T + c (fp32)
__device__ __nv_bfloat16  g_xhi[(size_t)MTOT * DD];
__device__ __nv_bfloat16  g_xlo[(size_t)MTOT * DD];
__device__ float          g_wut[DD * DD];             // Wu^T (fp32)
__device__ float          g_w2[DD * DD];              // W2 = Wf*Wu (fp32)
__device__ __nv_bfloat16  g_wuthi[DD * DD];
__device__ __nv_bfloat16  g_wutlo[DD * DD];
__device__ __nv_bfloat16  g_wfhi[DD * DD];
__device__ __nv_bfloat16  g_wflo[DD * DD];
__device__ __nv_bfloat16  g_w2hi[DD * DD];
__device__ __nv_bfloat16  g_w2lo[DD * DD];
__device__ float          g_c[DD];                    // c = Wf*bu
__device__ float          g_zero[DD];                 // stays zero (never written)
// chunked-scan summaries
__device__ float g_Ap[NCH * NCD];
__device__ float g_Be[NCH * NCD];
__device__ float g_cin[NCH * NCD];

// ---------------------------------------------------------------------------
// PTX helpers (base-target only: cp.async / ldmatrix / mma.sync — no tcgen05,
// which requires the sm_103a '.a' target the harness's nvcc does not emit)
// ---------------------------------------------------------------------------
__device__ __forceinline__ uint32_t smem_u32(const void* p) {
    uint32_t a;
    asm("{ .reg .u64 t; cvta.to.shared.u64 t, %1; cvt.u32.u64 %0, t; }" : "=r"(a) : "l"(p));
    return a;
}
__device__ __forceinline__ void cp16(uint32_t dst, const void* src) {
    asm volatile("cp.async.cg.shared.global [%0], [%1], 16;" :: "r"(dst), "l"(src));
}
__device__ __forceinline__ void cp_commit() {
    asm volatile("cp.async.commit_group;" ::: "memory");
}
template<int N>
__device__ __forceinline__ void cp_wait() {
    asm volatile("cp.async.wait_group %0;" :: "n"(N) : "memory");
}
__device__ __forceinline__ void ldm_x4(uint32_t* r, uint32_t addr) {
    asm volatile("ldmatrix.sync.aligned.m8n8.x4.shared.b16 {%0,%1,%2,%3}, [%4];"
                 : "=r"(r[0]), "=r"(r[1]), "=r"(r[2]), "=r"(r[3]) : "r"(addr));
}
__device__ __forceinline__ void mma16816(float* d, const uint32_t* a, const uint32_t* b) {
    asm volatile(
        "mma.sync.aligned.m16n8k16.row.col.f32.bf16.bf16.f32 "
        "{%0,%1,%2,%3}, {%4,%5,%6,%7}, {%8,%9}, {%0,%1,%2,%3};"
        : "+f"(d[0]), "+f"(d[1]), "+f"(d[2]), "+f"(d[3])
        : "r"(a[0]), "r"(a[1]), "r"(a[2]), "r"(a[3]), "r"(b[0]), "r"(b[1]));
}

// ---------------------------------------------------------------------------
// Split-bf16 GEMM: C[M,N] = Ahi*Bhi^T + Ahi*Blo^T + Alo*Bhi^T + bias, fp32 acc.
// Template MTILES: CTA tile (64*MTILES) x 128, BK=32, 8 warps (4x2),
// warp tile (16*MTILES) x 64. 2-stage cp.async pipeline, 1 barrier/k-block.
// K = DD = 1024 fixed; C row stride = DD.
// ---------------------------------------------------------------------------
#define BN 128
#define BKK 32
#define ASTR 40                       // 32 + 8 pad bf16 -> 80B rows, conflict-free
#define BTILE_B (128 * ASTR * 2)      // 10240 B (B operand tile, 128 rows)
#define NKB (DD / BKK)                // 32

template<int MTILES>
__global__ __launch_bounds__(256, 2)
void gemm_mma_split(const __nv_bfloat16* __restrict__ Ahi,
                    const __nv_bfloat16* __restrict__ Alo,
                    const __nv_bfloat16* __restrict__ Bhi,
                    const __nv_bfloat16* __restrict__ Blo,
                    const float* __restrict__ bias,
                    float* __restrict__ C)
{
    constexpr int BMT     = 64 * MTILES;
    constexpr int ATILE_B = BMT * ASTR * 2;
    constexpr int STAGE_B = 2 * ATILE_B + 2 * BTILE_B;

    extern __shared__ __align__(16) char smem[];
    const uint32_t sb = smem_u32(smem);

    const int tid  = threadIdx.x;
    const int wid  = tid >> 5;
    const int lane = tid & 31;
    const int wm   = wid & 3;    // warp row (M): 0..3
    const int wn   = wid >> 2;   // warp col (N): 0..1
    const int bx   = blockIdx.x; // N tile
    const int by   = blockIdx.y; // M tile

    // loader mapping: thread owns rows r0 (+64*j) at 16B-chunk c16
    const int r0  = tid >> 2;
    const int c16 = tid & 3;
    const __nv_bfloat16* Ah0 = Ahi + (size_t)(by * BMT + r0) * DD + c16 * 8;
    const __nv_bfloat16* Al0 = Alo + (size_t)(by * BMT + r0) * DD + c16 * 8;
    const __nv_bfloat16* Bh0 = Bhi + (size_t)(bx * BN + r0) * DD + c16 * 8;
    const __nv_bfloat16* Bl0 = Blo + (size_t)(bx * BN + r0) * DD + c16 * 8;
    const uint32_t dstb = (uint32_t)(r0 * 80 + c16 * 16);

    // ldmatrix addressing
    const int a_row = (lane & 7) + ((lane >> 3) & 1) * 8;
    const int a_col = (lane >> 4) * 8;
    const int b_row = (lane & 7) + (lane >> 4) * 8;
    const int b_col = ((lane >> 3) & 1) * 8;

    float acc[MTILES][8][4];
    #pragma unroll
    for (int i = 0; i < MTILES; i++)
        #pragma unroll
        for (int j = 0; j < 8; j++)
            #pragma unroll
            for (int q = 0; q < 4; q++)
                acc[i][j][q] = 0.0f;

    auto issue = [&](int kb, int st) {
        const uint32_t stg = sb + st * STAGE_B;
        const int ko = kb * BKK;
        #pragma unroll
        for (int j = 0; j < MTILES; j++) {
            const size_t ro = (size_t)j * 64 * DD;
            const uint32_t so = (uint32_t)(j * 64 * 80);
            cp16(stg + 0 * ATILE_B + dstb + so, Ah0 + ro + ko);
            cp16(stg + 1 * ATILE_B + dstb + so, Al0 + ro + ko);
        }
        #pragma unroll
        for (int j = 0; j < 2; j++) {
            const size_t ro = (size_t)j * 64 * DD;
            const uint32_t so = (uint32_t)(j * 64 * 80);
            cp16(stg + 2 * ATILE_B + dstb + so, Bh0 + ro + ko);
            cp16(stg + 2 * ATILE_B + BTILE_B + dstb + so, Bl0 + ro + ko);
        }
        cp_commit();
    };

    issue(0, 0);

    for (int kb = 0; kb < NKB; kb++) {
        const int st = kb & 1;
        cp_wait<0>();
        __syncthreads();                  // stage `st` visible; prev compute done
        if (kb + 1 < NKB) issue(kb + 1, st ^ 1);   // overlap next load w/ compute

        const uint32_t stg = sb + st * STAGE_B;
        #pragma unroll
        for (int ks = 0; ks < 2; ks++) {
            uint32_t aH[MTILES][4], aL[MTILES][4];
            #pragma unroll
            for (int mt = 0; mt < MTILES; mt++) {
                const uint32_t ra = (uint32_t)(
                    ((wm * 16 * MTILES + mt * 16 + a_row) * ASTR + ks * 16 + a_col) * 2);
                ldm_x4(aH[mt], stg + 0 * ATILE_B + ra);
                ldm_x4(aL[mt], stg + 1 * ATILE_B + ra);
            }
            #pragma unroll
            for (int g = 0; g < 4; g++) {
                const uint32_t rb = (uint32_t)(
                    ((wn * 64 + g * 16 + b_row) * ASTR + ks * 16 + b_col) * 2);
                uint32_t bH[4], bL[4];
                ldm_x4(bH, stg + 2 * ATILE_B + rb);
                ldm_x4(bL, stg + 2 * ATILE_B + BTILE_B + rb);
                #pragma unroll
                for (int mt = 0; mt < MTILES; mt++) {
                    mma16816(acc[mt][2 * g + 0], aH[mt], bH);
                    mma16816(acc[mt][2 * g + 1], aH[mt], bH + 2);
                    mma16816(acc[mt][2 * g + 0], aH[mt], bL);
                    mma16816(acc[mt][2 * g + 1], aH[mt], bL + 2);
                    mma16816(acc[mt][2 * g + 0], aL[mt], bH);
                    mma16816(acc[mt][2 * g + 1], aL[mt], bH + 2);
                }
            }
        }
    }

    // ---- epilogue: bias add + store (fp32) ----
    const int crow = by * BMT + wm * 16 * MTILES + (lane >> 2);
    const int ccol = bx * BN + wn * 64 + (lane & 3) * 2;
    #pragma unroll
    for (int mt = 0; mt < MTILES; mt++) {
        #pragma unroll
        for (int nt = 0; nt < 8; nt++) {
            const int gn = ccol + nt * 8;
            const float2 bv = *(const float2*)(bias + gn);
            float2 o0, o1;
            o0.x = acc[mt][nt][0] + bv.x;
            o0.y = acc[mt][nt][1] + bv.y;
            o1.x = acc[mt][nt][2] + bv.x;
            o1.y = acc[mt][nt][3] + bv.y;
            *(float2*)(C + (size_t)(crow + mt * 16) * DD + gn)     = o0;
            *(float2*)(C + (size_t)(crow + mt * 16 + 8) * DD + gn) = o1;
        }
    }
}

// ---------------------------------------------------------------------------
// fp32 -> (hi, lo) bf16 split, vectorized
// ---------------------------------------------------------------------------
__global__ void split_kernel(const float* __restrict__ in,
                             __nv_bfloat16* __restrict__ hi,
                             __nv_bfloat16* __restrict__ lo, int n4)
{
    for (int i = blockIdx.x * blockDim.x + threadIdx.x; i < n4; i += gridDim.x * blockDim.x) {
        const float4 v = ((const float4*)in)[i];
        __nv_bfloat16 hx = __float2bfloat16_rn(v.x);
        __nv_bfloat16 hy = __float2bfloat16_rn(v.y);
        __nv_bfloat16 hz = __float2bfloat16_rn(v.z);
        __nv_bfloat16 hw = __float2bfloat16_rn(v.w);
        __nv_bfloat162* h2 = (__nv_bfloat162*)hi;
        __nv_bfloat162* l2 = (__nv_bfloat162*)lo;
        h2[2 * i + 0] = __nv_bfloat162(hx, hy);
        h2[2 * i + 1] = __nv_bfloat162(hz, hw);
        l2[2 * i + 0] = __nv_bfloat162(__float2bfloat16_rn(v.x - __bfloat162float(hx)),
                                       __float2bfloat16_rn(v.y - __bfloat162float(hy)));
        l2[2 * i + 1] = __nv_bfloat162(__float2bfloat16_rn(v.z - __bfloat162float(hz)),
                                       __float2bfloat16_rn(v.w - __bfloat162float(hw)));
    }
}

// ---------------------------------------------------------------------------
// 1024x1024 fp32 transpose (for Wu -> Wu^T)
// ---------------------------------------------------------------------------
__global__ void transpose_k(const float* __restrict__ in, float* __restrict__ out)
{
    __shared__ float t[32][33];
    const int x  = blockIdx.x * 32 + threadIdx.x;
    const int y0 = blockIdx.y * 32 + threadIdx.y;
    #pragma unroll
    for (int j = 0; j < 4; j++)
        t[threadIdx.y + j * 8][threadIdx.x] = in[(size_t)(y0 + j * 8) * DD + x];
    __syncthreads();
    const int x2  = blockIdx.y * 32 + threadIdx.x;
    const int y2 = blockIdx.x * 32 + threadIdx.y;
    #pragma unroll
    for (int j = 0; j < 4; j++)
        out[(size_t)(y2 + j * 8) * DD + x2] = t[threadIdx.x][threadIdx.y + j * 8];
}

// ---------------------------------------------------------------------------
// c[e] = sum_d Wf[e,d] * bu[d]   (one block per e)
// ---------------------------------------------------------------------------
__global__ void bias_proj(const float* __restrict__ Wf,
                          const float* __restrict__ bu,
                          float* __restrict__ c)
{
    __shared__ float red[8];
    const int e = blockIdx.x;
    float s = 0.0f;
    for (int d = threadIdx.x; d < DD; d += 256)
        s += Wf[(size_t)e * DD + d] * bu[d];
    #pragma unroll
    for (int o = 16; o > 0; o >>= 1)
        s += __shfl_down_sync(0xffffffffu, s, o);
    if ((threadIdx.x & 31) == 0) red[threadIdx.x >> 5] = s;
    __syncthreads();
    if (threadIdx.x == 0) {
        float t = 0.0f;
        #pragma unroll
        for (int w = 0; w < 8; w++) t += red[w];
        c[e] = t;
    }
}

// ---------------------------------------------------------------------------
// Chunked scan over y: out_t = scan(m_t * y_t) + bf.
// pass1 computes per-chunk (A_prod, B_end); combine chains summaries;
// pass2 recomputes with correct carry-in and writes fp32 output directly.
// ---------------------------------------------------------------------------
__device__ __forceinline__ float get_decay(const float* decay_p) {
    return 1.0f / (1.0f + expf(-decay_p[0]));
}

__global__ void scan_pass1(const float* __restrict__ y,
                           const float* __restrict__ mask,
                           const float* __restrict__ decay_p,
                           float* __restrict__ Ap, float* __restrict__ Be)
{
    const int g  = blockIdx.x * blockDim.x + threadIdx.x;  // 0..65535
    const int ch = g >> 13;
    const int cd = g & (NCD - 1);
    const int b  = cd >> 10;
    const int d  = cd & (DD - 1);
    const float decay = get_decay(decay_p);

    const float* mrow = mask + (size_t)b * SS + ch * CHS;
    const float* p = y + ((size_t)b * SS + (size_t)ch * CHS) * DD + d;

    float A = 1.0f, acc = 0.0f;
    for (int s = 0; s < CHS; s += 8) {
        float u[8], mm[8];
        #pragma unroll
        for (int i = 0; i < 8; i++) {
            u[i]  = p[(size_t)(s + i) * DD];
            mm[i] = mrow[s + i];
        }
        #pragma unroll
        for (int i = 0; i < 8; i++) {
            const float a = mm[i] * decay + (1.0f - mm[i]);
            acc = fmaf(a, acc, mm[i] * u[i]);
            A *= a;
        }
    }
    Ap[g] = A;
    Be[g] = acc;
}

__global__ void scan_combine(const float* __restrict__ Ap,
                             const float* __restrict__ Be,
                             float* __restrict__ cin)
{
    const int g = blockIdx.x * blockDim.x + threadIdx.x;   // 0..8191
    float carry = 0.0f;
    #pragma unroll
    for (int ch = 0; ch < NCH; ch++) {
        cin[ch * NCD + g] = carry;
        carry = fmaf(Ap[ch * NCD + g], carry, Be[ch * NCD + g]);
    }
}

__global__ void scan_pass2(const float* __restrict__ y,
                           const float* __restrict__ mask,
                           const float* __restrict__ decay_p,
                           const float* __restrict__ cin,
                           const float* __restrict__ bf,
                           float* __restrict__ out)
{
    const int g  = blockIdx.x * blockDim.x + threadIdx.x;  // 0..65535
    const int ch = g >> 13;
    const int cd = g & (NCD - 1);
    const int b  = cd >> 10;
    const int d  = cd & (DD - 1);
    const float decay = get_decay(decay_p);
    const float bfv = bf[d];

    const float* mrow = mask + (size_t)b * SS + ch * CHS;
    const size_t base = ((size_t)b * SS + (size_t)ch * CHS) * DD + d;
    const float* p = y + base;
    float* po = out + base;

    float carry = cin[g];
    for (int s = 0; s < CHS; s += 8) {
        float u[8], mm[8];
        #pragma unroll
        for (int i = 0; i < 8; i++) {
            u[i]  = p[(size_t)(s + i) * DD];
            mm[i] = mrow[s + i];
        }
        #pragma unroll
        for (int i = 0; i < 8; i++) {
            const float a = mm[i] * decay + (1.0f - mm[i]);
            carry = fmaf(a, carry, mm[i] * u[i]);
            po[(size_t)(s + i) * DD] = carry + bfv;
        }
    }
}

// ---------------------------------------------------------------------------
// kernel_launch
// Inputs: 0:x (B,S,D)  1:mask (B,S)  2:Wu (D,D)  3:bu (D)
//         4:Wf (D,D)   5:bf (D)      6:decay_param (1)
//
// Math: out = scan(m*(x*Wu^T + bu))*Wf^T + bf  ==  scan(m*(x*W2^T + c)) + bf
//       with W2 = Wf*Wu (scan coeffs are per-(b,t) scalars; linearity).
// ---------------------------------------------------------------------------
extern "C" void kernel_launch(void* const* d_in, const int* in_sizes, int n_in,
                              void* d_out, int out_size)
{
    const float* x     = (const float*)d_in[0];
    const float* mask  = (const float*)d_in[1];
    const float* Wu    = (const float*)d_in[2];
    const float* bu    = (const float*)d_in[3];
    const float* Wf    = (const float*)d_in[4];
    const float* bf    = (const float*)d_in[5];
    const float* decay = (const float*)d_in[6];
    float* out = (float*)d_out;

    float *y, *wut, *w2, *cvec, *zero, *Ap, *Be, *cin;
    __nv_bfloat16 *xhi, *xlo, *wuthi, *wutlo, *wfhi, *wflo, *w2hi, *w2lo;
    cudaGetSymbolAddress((void**)&y,     g_y);
    cudaGetSymbolAddress((void**)&xhi,   g_xhi);
    cudaGetSymbolAddress((void**)&xlo,   g_xlo);
    cudaGetSymbolAddress((void**)&wut,   g_wut);
    cudaGetSymbolAddress((void**)&w2,    g_w2);
    cudaGetSymbolAddress((void**)&wuthi, g_wuthi);
    cudaGetSymbolAddress((void**)&wutlo, g_wutlo);
    cudaGetSymbolAddress((void**)&wfhi,  g_wfhi);
    cudaGetSymbolAddress((void**)&wflo,  g_wflo);
    cudaGetSymbolAddress((void**)&w2hi,  g_w2hi);
    cudaGetSymbolAddress((void**)&w2lo,  g_w2lo);
    cudaGetSymbolAddress((void**)&cvec,  g_c);
    cudaGetSymbolAddress((void**)&zero,  g_zero);
    cudaGetSymbolAddress((void**)&Ap,    g_Ap);
    cudaGetSymbolAddress((void**)&Be,    g_Be);
    cudaGetSymbolAddress((void**)&cin,   g_cin);

    constexpr int SMEM2 = 2 * (2 * 128 * ASTR * 2 + 2 * BTILE_B);  // MTILES=2
    constexpr int SMEM1 = 2 * (2 * 64  * ASTR * 2 + 2 * BTILE_B);  // MTILES=1
    cudaFuncSetAttribute(gemm_mma_split<2>, cudaFuncAttributeMaxDynamicSharedMemorySize, SMEM2);
    cudaFuncSetAttribute(gemm_mma_split<1>, cudaFuncAttributeMaxDynamicSharedMemorySize, SMEM1);

    // --- weight prep (small) ---
    transpose_k<<<dim3(32, 32), dim3(32, 8)>>>(Wu, wut);          // Wu^T
    split_kernel<<<128, 256>>>(wut, wuthi, wutlo, DD * DD / 4);
    split_kernel<<<128, 256>>>(Wf,  wfhi,  wflo,  DD * DD / 4);
    bias_proj<<<DD, 256>>>(Wf, bu, cvec);                         // c = Wf*bu

    // W2 = Wf * Wu: C[e,d'] = sum_d Wf[e,d]*WuT[d',d]  (NT, M=1024)
    gemm_mma_split<1><<<dim3(DD / BN, 1024 / 64), 256, SMEM1>>>(
        wfhi, wflo, wuthi, wutlo, zero, w2);
    split_kernel<<<128, 256>>>(w2, w2hi, w2lo, DD * DD / 4);

    // --- big path ---
    split_kernel<<<2048, 256>>>(x, xhi, xlo, MTOT * DD / 4);

    // y = x*W2^T + c   (the single big GEMM)
    gemm_mma_split<2><<<dim3(DD / BN, MTOT / 128), 256, SMEM2>>>(
        xhi, xlo, w2hi, w2lo, cvec, y);

    // out = scan(m*y) + bf  (chunked parallel scan, writes d_out directly)
    scan_pass1<<<NCH * NCD / 256, 256>>>(y, mask, decay, Ap, Be);
    scan_combine<<<NCD / 256, 256>>>(Ap, Be, cin);
    scan_pass2<<<NCH * NCD / 256, 256>>>(y, mask, decay, cin, bf, out);
}

// round 13
// speedup vs baseline: 4.4461x; 1.3737x over previous
#include <cuda_runtime.h>
#include <cuda_bf16.h>
#include <math.h>
#include <stdint.h>

// Problem constants (fixed by the dataset)
#define BB 8
#define SS 4096
#define DD 1024
#define MTOT (BB * SS)   // 32768

#define NCH 32
#define CHS (SS / NCH)   // 128 steps per chunk
#define NCD (BB * DD)    // 8192 chains

// ---------------------------------------------------------------------------
// Scratch (device globals; no allocation allowed). Zero-initialized at load.
// ---------------------------------------------------------------------------
__device__ float          g_y[(size_t)MTOT * DD];     // y = x*W2^T + c (fp32)
__device__ float          g_wut[DD * DD];             // Wu^T (fp32)
__device__ float          g_w2[DD * DD];              // W2 = Wf*Wu (fp32)
__device__ __nv_bfloat16  g_wuthi[DD * DD];
__device__ __nv_bfloat16  g_wutlo[DD * DD];
__device__ __nv_bfloat16  g_wfhi[DD * DD];
__device__ __nv_bfloat16  g_wflo[DD * DD];
__device__ __nv_bfloat16  g_w2hi[DD * DD];
__device__ __nv_bfloat16  g_w2lo[DD * DD];
__device__ float          g_c[DD];                    // c = Wf*bu
__device__ float          g_zero[DD];                 // stays zero (never written)
// chunked-scan summaries
__device__ float g_Ap[NCH * NCD];
__device__ float g_Be[NCH * NCD];
__device__ float g_cin[NCH * NCD];

// ---------------------------------------------------------------------------
// PTX helpers (base-target only: cp.async / ldmatrix / mma.sync — no tcgen05,
// which requires the sm_103a '.a' target the harness's nvcc does not emit)
// ---------------------------------------------------------------------------
__device__ __forceinline__ uint32_t smem_u32(const void* p) {
    uint32_t a;
    asm("{ .reg .u64 t; cvta.to.shared.u64 t, %1; cvt.u32.u64 %0, t; }" : "=r"(a) : "l"(p));
    return a;
}
__device__ __forceinline__ void cp16(uint32_t dst, const void* src) {
    asm volatile("cp.async.cg.shared.global [%0], [%1], 16;" :: "r"(dst), "l"(src));
}
__device__ __forceinline__ void cp_commit() {
    asm volatile("cp.async.commit_group;" ::: "memory");
}
template<int N>
__device__ __forceinline__ void cp_wait() {
    asm volatile("cp.async.wait_group %0;" :: "n"(N) : "memory");
}
__device__ __forceinline__ void ldm_x4(uint32_t* r, uint32_t addr) {
    asm volatile("ldmatrix.sync.aligned.m8n8.x4.shared.b16 {%0,%1,%2,%3}, [%4];"
                 : "=r"(r[0]), "=r"(r[1]), "=r"(r[2]), "=r"(r[3]) : "r"(addr));
}
__device__ __forceinline__ void mma16816(float* d, const uint32_t* a, const uint32_t* b) {
    asm volatile(
        "mma.sync.aligned.m16n8k16.row.col.f32.bf16.bf16.f32 "
        "{%0,%1,%2,%3}, {%4,%5,%6,%7}, {%8,%9}, {%0,%1,%2,%3};"
        : "+f"(d[0]), "+f"(d[1]), "+f"(d[2]), "+f"(d[3])
        : "r"(a[0]), "r"(a[1]), "r"(a[2]), "r"(a[3]), "r"(b[0]), "r"(b[1]));
}
__device__ __forceinline__ uint32_t pack_bf16x2(float a, float b) {
    __nv_bfloat162 h(__float2bfloat16_rn(a), __float2bfloat16_rn(b));
    return *reinterpret_cast<uint32_t*>(&h);
}

#define BN 128
#define BKK 32
#define ASTR 40                       // 32 + 8 pad bf16 -> 80B rows, conflict-free
#define TILE80 (128 * 80)             // 10240 B: one padded bf16 tile (128 rows)
#define NKB (DD / BKK)                // 32

// ---------------------------------------------------------------------------
// Big fused GEMM: y[M,N] = x*W2hi^T + x*W2lo^T (split applied to x on the fly)
//                 + bias.  x is fp32; per k-block it is cp.async'd raw, then
//                 converted in-smem to (hi, lo) bf16 before the MMA phase.
// CTA tile 128x128, 8 warps (4x2), warp tile 32x64.
// smem: raw[2]*16KB + Acvt(hi+lo) 20KB + B(hi+lo)[2] 40KB = 92KB, 2 CTA/SM.
// ---------------------------------------------------------------------------
#define RAW_B 16384
#define OFF_RAW 0
#define OFF_ACV (2 * RAW_B)                   // 32768
#define OFF_B   (OFF_ACV + 2 * TILE80)        // 53248
#define FUSED_SMEM (OFF_B + 2 * 2 * TILE80)   // 94208

__global__ __launch_bounds__(256, 2)
void gemm_xf32(const float* __restrict__ X,
               const __nv_bfloat16* __restrict__ Bhi,
               const __nv_bfloat16* __restrict__ Blo,
               const float* __restrict__ bias,
               float* __restrict__ C)
{
    extern __shared__ __align__(16) char smem[];
    const uint32_t sb = smem_u32(smem);

    const int tid  = threadIdx.x;
    const int wid  = tid >> 5;
    const int lane = tid & 31;
    const int wm   = wid & 3;    // warp row (M)
    const int wn   = wid >> 2;   // warp col (N)
    const int bx   = blockIdx.x; // N tile
    const int by   = blockIdx.y; // M tile

    // B loader: r0 = tid>>2 (0..63), c16 = tid&3; rows r0, r0+64
    const int r0  = tid >> 2;
    const int c16 = tid & 3;
    const __nv_bfloat16* Bh0 = Bhi + (size_t)(bx * BN + r0) * DD + c16 * 8;
    const __nv_bfloat16* Bl0 = Blo + (size_t)(bx * BN + r0) * DD + c16 * 8;
    const uint32_t dstb = (uint32_t)(r0 * 80 + c16 * 16);

    // convert mapping: thread -> row (0..127), half (0..1): 16 floats
    const int cv_row  = tid >> 1;
    const int cv_half = tid & 1;

    // ldmatrix addressing
    const int a_row = (lane & 7) + ((lane >> 3) & 1) * 8;
    const int a_col = (lane >> 4) * 8;
    const int b_row = (lane & 7) + (lane >> 4) * 8;
    const int b_col = ((lane >> 3) & 1) * 8;

    float acc[2][8][4];
    #pragma unroll
    for (int i = 0; i < 2; i++)
        #pragma unroll
        for (int j = 0; j < 8; j++)
            #pragma unroll
            for (int q = 0; q < 4; q++)
                acc[i][j][q] = 0.0f;

    auto issue = [&](int kb, int st) {
        const int ko = kb * BKK;
        // raw fp32 A tile: 128 rows x 128B
        const uint32_t rawst = sb + OFF_RAW + st * RAW_B;
        #pragma unroll
        for (int j = 0; j < 4; j++) {
            const int u = tid + j * 256;
            const int row = u >> 3;
            const int cc  = u & 7;
            cp16(rawst + row * 128 + cc * 16,
                 X + (size_t)(by * 128 + row) * DD + ko + cc * 4);
        }
        // B hi/lo bf16 tiles (padded)
        const uint32_t bst = sb + OFF_B + st * (2 * TILE80);
        #pragma unroll
        for (int j = 0; j < 2; j++) {
            const size_t ro = (size_t)j * 64 * DD;
            const uint32_t so = (uint32_t)(j * 64 * 80);
            cp16(bst + dstb + so, Bh0 + ro + ko);
            cp16(bst + TILE80 + dstb + so, Bl0 + ro + ko);
        }
        cp_commit();
    };

    issue(0, 0);

    for (int kb = 0; kb < NKB; kb++) {
        const int st = kb & 1;
        cp_wait<0>();
        __syncthreads();                 // raw[st]+B[st] ready; MMA kb-1 done
        if (kb + 1 < NKB) issue(kb + 1, st ^ 1);

        // ---- in-smem split: raw fp32 -> Acvt hi/lo bf16 (padded) ----
        {
            const char* src = smem + OFF_RAW + st * RAW_B + cv_row * 128 + cv_half * 64;
            float f[16];
            #pragma unroll
            for (int i = 0; i < 4; i++) {
                const float4 v = *(const float4*)(src + i * 16);
                f[4*i+0] = v.x; f[4*i+1] = v.y; f[4*i+2] = v.z; f[4*i+3] = v.w;
            }
            uint32_t h[8], l[8];
            #pragma unroll
            for (int i = 0; i < 8; i++) {
                const float fa = f[2*i], fbv = f[2*i+1];
                h[i] = pack_bf16x2(fa, fbv);
                const float ra = fa - __bfloat162float(__float2bfloat16_rn(fa));
                const float rb = fbv - __bfloat162float(__float2bfloat16_rn(fbv));
                l[i] = pack_bf16x2(ra, rb);
            }
            const uint32_t dsth = sb + OFF_ACV + cv_row * 80 + cv_half * 32;
            const uint32_t dstl = dsth + TILE80;
            asm volatile("st.shared.v4.b32 [%0], {%1,%2,%3,%4};"
                         :: "r"(dsth), "r"(h[0]), "r"(h[1]), "r"(h[2]), "r"(h[3]) : "memory");
            asm volatile("st.shared.v4.b32 [%0], {%1,%2,%3,%4};"
                         :: "r"(dsth + 16), "r"(h[4]), "r"(h[5]), "r"(h[6]), "r"(h[7]) : "memory");
            asm volatile("st.shared.v4.b32 [%0], {%1,%2,%3,%4};"
                         :: "r"(dstl), "r"(l[0]), "r"(l[1]), "r"(l[2]), "r"(l[3]) : "memory");
            asm volatile("st.shared.v4.b32 [%0], {%1,%2,%3,%4};"
                         :: "r"(dstl + 16), "r"(l[4]), "r"(l[5]), "r"(l[6]), "r"(l[7]) : "memory");
        }
        __syncthreads();                 // Acvt visible

        const uint32_t stgA = sb + OFF_ACV;
        const uint32_t stgB = sb + OFF_B + st * (2 * TILE80);
        #pragma unroll
        for (int ks = 0; ks < 2; ks++) {
            uint32_t aH[2][4], aL[2][4];
            #pragma unroll
            for (int mt = 0; mt < 2; mt++) {
                const uint32_t ra =
                    (uint32_t)(((wm * 32 + mt * 16 + a_row) * ASTR + ks * 16 + a_col) * 2);
                ldm_x4(aH[mt], stgA + ra);
                ldm_x4(aL[mt], stgA + TILE80 + ra);
            }
            #pragma unroll
            for (int g = 0; g < 4; g++) {
                const uint32_t rb =
                    (uint32_t)(((wn * 64 + g * 16 + b_row) * ASTR + ks * 16 + b_col) * 2);
                uint32_t bH[4], bL[4];
                ldm_x4(bH, stgB + rb);
                ldm_x4(bL, stgB + TILE80 + rb);
                #pragma unroll
                for (int mt = 0; mt < 2; mt++) {
                    mma16816(acc[mt][2 * g + 0], aH[mt], bH);
                    mma16816(acc[mt][2 * g + 1], aH[mt], bH + 2);
                    mma16816(acc[mt][2 * g + 0], aH[mt], bL);
                    mma16816(acc[mt][2 * g + 1], aH[mt], bL + 2);
                    mma16816(acc[mt][2 * g + 0], aL[mt], bH);
                    mma16816(acc[mt][2 * g + 1], aL[mt], bH + 2);
                }
            }
        }
    }

    // ---- epilogue: bias add + store (fp32) ----
    const int crow = by * 128 + wm * 32 + (lane >> 2);
    const int ccol = bx * BN + wn * 64 + (lane & 3) * 2;
    #pragma unroll
    for (int mt = 0; mt < 2; mt++) {
        #pragma unroll
        for (int nt = 0; nt < 8; nt++) {
            const int gn = ccol + nt * 8;
            const float2 bv = *(const float2*)(bias + gn);
            float2 o0, o1;
            o0.x = acc[mt][nt][0] + bv.x;
            o0.y = acc[mt][nt][1] + bv.y;
            o1.x = acc[mt][nt][2] + bv.x;
            o1.y = acc[mt][nt][3] + bv.y;
            *(float2*)(C + (size_t)(crow + mt * 16) * DD + gn)     = o0;
            *(float2*)(C + (size_t)(crow + mt * 16 + 8) * DD + gn) = o1;
        }
    }
}

// ---------------------------------------------------------------------------
// Small split-bf16 GEMM (pre-split operands) for W2 = Wf*Wu. M tile 64.
// Each thread loads BOTH Ahi and Alo chunks (r0 spans 0..63 only).
// ---------------------------------------------------------------------------
#define SM1_STAGE (2 * 64 * 80 + 2 * TILE80)
#define SM1_SMEM  (2 * SM1_STAGE)

__global__ __launch_bounds__(256, 2)
void gemm_w2(const __nv_bfloat16* __restrict__ Ahi,
             const __nv_bfloat16* __restrict__ Alo,
             const __nv_bfloat16* __restrict__ Bhi,
             const __nv_bfloat16* __restrict__ Blo,
             const float* __restrict__ bias,
             float* __restrict__ C)
{
    constexpr int ATILE_B = 64 * 80;
    extern __shared__ __align__(16) char smem[];
    const uint32_t sb = smem_u32(smem);

    const int tid  = threadIdx.x;
    const int wid  = tid >> 5;
    const int lane = tid & 31;
    const int wm   = wid & 3;
    const int wn   = wid >> 2;
    const int bx   = blockIdx.x;
    const int by   = blockIdx.y;

    const int r0  = tid >> 2;    // 0..63
    const int c16 = tid & 3;
    const __nv_bfloat16* Ah0 = Ahi + (size_t)(by * 64 + r0) * DD + c16 * 8;
    const __nv_bfloat16* Al0 = Alo + (size_t)(by * 64 + r0) * DD + c16 * 8;
    const __nv_bfloat16* Bh0 = Bhi + (size_t)(bx * BN + r0) * DD + c16 * 8;
    const __nv_bfloat16* Bl0 = Blo + (size_t)(bx * BN + r0) * DD + c16 * 8;
    const uint32_t dsta = (uint32_t)(r0 * 80 + c16 * 16);
    const uint32_t dstb = dsta;

    const int a_row = (lane & 7) + ((lane >> 3) & 1) * 8;
    const int a_col = (lane >> 4) * 8;
    const int b_row = (lane & 7) + (lane >> 4) * 8;
    const int b_col = ((lane >> 3) & 1) * 8;

    float acc[8][4];
    #pragma unroll
    for (int j = 0; j < 8; j++)
        #pragma unroll
        for (int q = 0; q < 4; q++)
            acc[j][q] = 0.0f;

    auto issue = [&](int kb, int st) {
        const uint32_t stg = sb + st * SM1_STAGE;
        const int ko = kb * BKK;
        cp16(stg + dsta, Ah0 + ko);                    // Ahi tile (64 rows)
        cp16(stg + ATILE_B + dsta, Al0 + ko);          // Alo tile (64 rows)
        #pragma unroll
        for (int j = 0; j < 2; j++) {
            const size_t ro = (size_t)j * 64 * DD;
            const uint32_t so = (uint32_t)(j * 64 * 80);
            cp16(stg + 2 * ATILE_B + dstb + so, Bh0 + ro + ko);
            cp16(stg + 2 * ATILE_B + TILE80 + dstb + so, Bl0 + ro + ko);
        }
        cp_commit();
    };

    issue(0, 0);
    for (int kb = 0; kb < NKB; kb++) {
        const int st = kb & 1;
        cp_wait<0>();
        __syncthreads();
        if (kb + 1 < NKB) issue(kb + 1, st ^ 1);

        const uint32_t stg = sb + st * SM1_STAGE;
        #pragma unroll
        for (int ks = 0; ks < 2; ks++) {
            uint32_t aH[4], aL[4];
            const uint32_t ra = (uint32_t)(((wm * 16 + a_row) * ASTR + ks * 16 + a_col) * 2);
            ldm_x4(aH, stg + ra);
            ldm_x4(aL, stg + ATILE_B + ra);
            #pragma unroll
            for (int g = 0; g < 4; g++) {
                const uint32_t rb = (uint32_t)(((wn * 64 + g * 16 + b_row) * ASTR + ks * 16 + b_col) * 2);
                uint32_t bH[4], bL[4];
                ldm_x4(bH, stg + 2 * ATILE_B + rb);
                ldm_x4(bL, stg + 2 * ATILE_B + TILE80 + rb);
                mma16816(acc[2 * g + 0], aH, bH);
                mma16816(acc[2 * g + 1], aH, bH + 2);
                mma16816(acc[2 * g + 0], aH, bL);
                mma16816(acc[2 * g + 1], aH, bL + 2);
                mma16816(acc[2 * g + 0], aL, bH);
                mma16816(acc[2 * g + 1], aL, bH + 2);
            }
        }
    }

    const int crow = by * 64 + wm * 16 + (lane >> 2);
    const int ccol = bx * BN + wn * 64 + (lane & 3) * 2;
    #pragma unroll
    for (int nt = 0; nt < 8; nt++) {
        const int gn = ccol + nt * 8;
        const float2 bv = *(const float2*)(bias + gn);
        float2 o0, o1;
        o0.x = acc[nt][0] + bv.x;
        o0.y = acc[nt][1] + bv.y;
        o1.x = acc[nt][2] + bv.x;
        o1.y = acc[nt][3] + bv.y;
        *(float2*)(C + (size_t)crow * DD + gn)       = o0;
        *(float2*)(C + (size_t)(crow + 8) * DD + gn) = o1;
    }
}

// ---------------------------------------------------------------------------
// fp32 -> (hi, lo) bf16 split (weights only now)
// ---------------------------------------------------------------------------
__global__ void split_kernel(const float* __restrict__ in,
                             __nv_bfloat16* __restrict__ hi,
                             __nv_bfloat16* __restrict__ lo, int n4)
{
    for (int i = blockIdx.x * blockDim.x + threadIdx.x; i < n4; i += gridDim.x * blockDim.x) {
        const float4 v = ((const float4*)in)[i];
        __nv_bfloat16 hx = __float2bfloat16_rn(v.x);
        __nv_bfloat16 hy = __float2bfloat16_rn(v.y);
        __nv_bfloat16 hz = __float2bfloat16_rn(v.z);
        __nv_bfloat16 hw = __float2bfloat16_rn(v.w);
        __nv_bfloat162* h2 = (__nv_bfloat162*)hi;
        __nv_bfloat162* l2 = (__nv_bfloat162*)lo;
        h2[2 * i + 0] = __nv_bfloat162(hx, hy);
        h2[2 * i + 1] = __nv_bfloat162(hz, hw);
        l2[2 * i + 0] = __nv_bfloat162(__float2bfloat16_rn(v.x - __bfloat162float(hx)),
                                       __float2bfloat16_rn(v.y - __bfloat162float(hy)));
        l2[2 * i + 1] = __nv_bfloat162(__float2bfloat16_rn(v.z - __bfloat162float(hz)),
                                       __float2bfloat16_rn(v.w - __bfloat162float(hw)));
    }
}

// ---------------------------------------------------------------------------
// 1024x1024 fp32 transpose (Wu -> Wu^T)
// ---------------------------------------------------------------------------
__global__ void transpose_k(const float* __restrict__ in, float* __restrict__ out)
{
    __shared__ float t[32][33];
    const int x  = blockIdx.x * 32 + threadIdx.x;
    const int y0 = blockIdx.y * 32 + threadIdx.y;
    #pragma unroll
    for (int j = 0; j < 4; j++)
        t[threadIdx.y + j * 8][threadIdx.x] = in[(size_t)(y0 + j * 8) * DD + x];
    __syncthreads();
    const int x2 = blockIdx.y * 32 + threadIdx.x;
    const int y2 = blockIdx.x * 32 + threadIdx.y;
    #pragma unroll
    for (int j = 0; j < 4; j++)
        out[(size_t)(y2 + j * 8) * DD + x2] = t[threadIdx.x][threadIdx.y + j * 8];
}

// ---------------------------------------------------------------------------
// c[e] = sum_d Wf[e,d] * bu[d]
// ---------------------------------------------------------------------------
__global__ void bias_proj(const float* __restrict__ Wf,
                          const float* __restrict__ bu,
                          float* __restrict__ c)
{
    __shared__ float red[8];
    const int e = blockIdx.x;
    float s = 0.0f;
    for (int d = threadIdx.x; d < DD; d += 256)
        s += Wf[(size_t)e * DD + d] * bu[d];
    #pragma unroll
    for (int o = 16; o > 0; o >>= 1)
        s += __shfl_down_sync(0xffffffffu, s, o);
    if ((threadIdx.x & 31) == 0) red[threadIdx.x >> 5] = s;
    __syncthreads();
    if (threadIdx.x == 0) {
        float t = 0.0f;
        #pragma unroll
        for (int w = 0; w < 8; w++) t += red[w];
        c[e] = t;
    }
}

// ---------------------------------------------------------------------------
// Chunked scan over y (float4 per thread, NCH=32 chunks of 128):
// out_t = scan(m_t * y_t) + bf
// ---------------------------------------------------------------------------
__device__ __forceinline__ float get_decay(const float* decay_p) {
    return 1.0f / (1.0f + expf(-decay_p[0]));
}

__global__ void scan_pass1(const float* __restrict__ y,
                           const float* __restrict__ mask,
                           const float* __restrict__ decay_p,
                           float* __restrict__ Ap, float* __restrict__ Be)
{
    const int g  = blockIdx.x * blockDim.x + threadIdx.x;  // 0..65535
    const int ch = g >> 11;                  // NCD/4 = 2048 threads per chunk
    const int q  = g & 2047;
    const int b  = q >> 8;                   // DD/4 = 256 per batch
    const int d  = (q & 255) * 4;
    const float decay = get_decay(decay_p);

    const float* mrow = mask + (size_t)b * SS + ch * CHS;
    const float* p = y + ((size_t)b * SS + (size_t)ch * CHS) * DD + d;

    float A = 1.0f;
    float4 acc = make_float4(0.f, 0.f, 0.f, 0.f);
    for (int s = 0; s < CHS; s += 8) {
        float4 u[8]; float mm[8];
        #pragma unroll
        for (int i = 0; i < 8; i++) {
            u[i]  = *(const float4*)(p + (size_t)(s + i) * DD);
            mm[i] = mrow[s + i];
        }
        #pragma unroll
        for (int i = 0; i < 8; i++) {
            const float a = mm[i] * decay + (1.0f - mm[i]);
            acc.x = fmaf(a, acc.x, mm[i] * u[i].x);
            acc.y = fmaf(a, acc.y, mm[i] * u[i].y);
            acc.z = fmaf(a, acc.z, mm[i] * u[i].z);
            acc.w = fmaf(a, acc.w, mm[i] * u[i].w);
            A *= a;
        }
    }
    const int o = ch * NCD + b * DD + d;
    *(float4*)(Be + o) = acc;
    *(float4*)(Ap + o) = make_float4(A, A, A, A);
}

__global__ void scan_combine(const float* __restrict__ Ap,
                             const float* __restrict__ Be,
                             float* __restrict__ cin)
{
    const int g = blockIdx.x * blockDim.x + threadIdx.x;   // 0..8191
    float carry = 0.0f;
    #pragma unroll
    for (int ch = 0; ch < NCH; ch++) {
        cin[ch * NCD + g] = carry;
        carry = fmaf(Ap[ch * NCD + g], carry, Be[ch * NCD + g]);
    }
}

__global__ void scan_pass2(const float* __restrict__ y,
                           const float* __restrict__ mask,
                           const float* __restrict__ decay_p,
                           const float* __restrict__ cin,
                           const float* __restrict__ bf,
                           float* __restrict__ out)
{
    const int g  = blockIdx.x * blockDim.x + threadIdx.x;  // 0..65535
    const int ch = g >> 11;
    const int q  = g & 2047;
    const int b  = q >> 8;
    const int d  = (q & 255) * 4;
    const float decay = get_decay(decay_p);
    const float4 bfv = *(const float4*)(bf + d);

    const float* mrow = mask + (size_t)b * SS + ch * CHS;
    const size_t base = ((size_t)b * SS + (size_t)ch * CHS) * DD + d;
    const float* p = y + base;
    float* po = out + base;

    float4 carry = *(const float4*)(cin + ch * NCD + b * DD + d);
    for (int s = 0; s < CHS; s += 8) {
        float4 u[8]; float mm[8];
        #pragma unroll
        for (int i = 0; i < 8; i++) {
            u[i]  = *(const float4*)(p + (size_t)(s + i) * DD);
            mm[i] = mrow[s + i];
        }
        #pragma unroll
        for (int i = 0; i < 8; i++) {
            const float a = mm[i] * decay + (1.0f - mm[i]);
            carry.x = fmaf(a, carry.x, mm[i] * u[i].x);
            carry.y = fmaf(a, carry.y, mm[i] * u[i].y);
            carry.z = fmaf(a, carry.z, mm[i] * u[i].z);
            carry.w = fmaf(a, carry.w, mm[i] * u[i].w);
            float4 o;
            o.x = carry.x + bfv.x; o.y = carry.y + bfv.y;
            o.z = carry.z + bfv.z; o.w = carry.w + bfv.w;
            *(float4*)(po + (size_t)(s + i) * DD) = o;
        }
    }
}

// ---------------------------------------------------------------------------
// kernel_launch
// Inputs: 0:x (B,S,D)  1:mask (B,S)  2:Wu (D,D)  3:bu (D)
//         4:Wf (D,D)   5:bf (D)      6:decay_param (1)
//
// Math: out = scan(m*(x*Wu^T + bu))*Wf^T + bf  ==  scan(m*(x*W2^T + c)) + bf
//       with W2 = Wf*Wu, c = Wf*bu (scan coeffs are per-(b,t) scalars).
// ---------------------------------------------------------------------------
extern "C" void kernel_launch(void* const* d_in, const int* in_sizes, int n_in,
                              void* d_out, int out_size)
{
    const float* x     = (const float*)d_in[0];
    const float* mask  = (const float*)d_in[1];
    const float* Wu    = (const float*)d_in[2];
    const float* bu    = (const float*)d_in[3];
    const float* Wf    = (const float*)d_in[4];
    const float* bf    = (const float*)d_in[5];
    const float* decay = (const float*)d_in[6];
    float* out = (float*)d_out;

    float *y, *wut, *w2, *cvec, *zero, *Ap, *Be, *cin;
    __nv_bfloat16 *wuthi, *wutlo, *wfhi, *wflo, *w2hi, *w2lo;
    cudaGetSymbolAddress((void**)&y,     g_y);
    cudaGetSymbolAddress((void**)&wut,   g_wut);
    cudaGetSymbolAddress((void**)&w2,    g_w2);
    cudaGetSymbolAddress((void**)&wuthi, g_wuthi);
    cudaGetSymbolAddress((void**)&wutlo, g_wutlo);
    cudaGetSymbolAddress((void**)&wfhi,  g_wfhi);
    cudaGetSymbolAddress((void**)&wflo,  g_wflo);
    cudaGetSymbolAddress((void**)&w2hi,  g_w2hi);
    cudaGetSymbolAddress((void**)&w2lo,  g_w2lo);
    cudaGetSymbolAddress((void**)&cvec,  g_c);
    cudaGetSymbolAddress((void**)&zero,  g_zero);
    cudaGetSymbolAddress((void**)&Ap,    g_Ap);
    cudaGetSymbolAddress((void**)&Be,    g_Be);
    cudaGetSymbolAddress((void**)&cin,   g_cin);

    cudaFuncSetAttribute(gemm_xf32, cudaFuncAttributeMaxDynamicSharedMemorySize, FUSED_SMEM);
    cudaFuncSetAttribute(gemm_w2,   cudaFuncAttributeMaxDynamicSharedMemorySize, SM1_SMEM);

    // --- weight prep (small) ---
    transpose_k<<<dim3(32, 32), dim3(32, 8)>>>(Wu, wut);          // Wu^T
    split_kernel<<<128, 256>>>(wut, wuthi, wutlo, DD * DD / 4);
    split_kernel<<<128, 256>>>(Wf,  wfhi,  wflo,  DD * DD / 4);
    bias_proj<<<DD, 256>>>(Wf, bu, cvec);                         // c = Wf*bu

    // W2 = Wf * Wu
    gemm_w2<<<dim3(DD / BN, 1024 / 64), 256, SM1_SMEM>>>(
        wfhi, wflo, wuthi, wutlo, zero, w2);
    split_kernel<<<128, 256>>>(w2, w2hi, w2lo, DD * DD / 4);

    // --- big path: y = x*W2^T + c (x split fused into the GEMM) ---
    gemm_xf32<<<dim3(DD / BN, MTOT / 128), 256, FUSED_SMEM>>>(
        x, w2hi, w2lo, cvec, y);

    // out = scan(m*y) + bf  (chunked parallel scan, writes d_out directly)
    scan_pass1<<<NCH * NCD / 4 / 256, 256>>>(y, mask, decay, Ap, Be);
    scan_combine<<<NCD / 256, 256>>>(Ap, Be, cin);
    scan_pass2<<<NCH * NCD / 4 / 256, 256>>>(y, mask, decay, cin, bf, out);
}

// round 14
// speedup vs baseline: 4.4956x; 1.0111x over previous
#include <cuda_runtime.h>
#include <cuda_bf16.h>
#include <math.h>
#include <stdint.h>

// Problem constants (fixed by the dataset)
#define BB 8
#define SS 4096
#define DD 1024
#define MTOT (BB * SS)   // 32768

#define NCH 32
#define CHS (SS / NCH)   // 128 steps per chunk == GEMM M-tile
#define NCD (BB * DD)    // 8192 chains

// ---------------------------------------------------------------------------
// Scratch (device globals; no allocation allowed). Zero-initialized at load.
// ---------------------------------------------------------------------------
__device__ float          g_y[(size_t)MTOT * DD];     // within-chunk zero-init scan of m*y
__device__ float          g_wut[DD * DD];             // Wu^T (fp32)
__device__ float          g_w2[DD * DD];              // W2 = Wf*Wu (fp32)
__device__ __nv_bfloat16  g_wuthi[DD * DD];
__device__ __nv_bfloat16  g_wutlo[DD * DD];
__device__ __nv_bfloat16  g_wfhi[DD * DD];
__device__ __nv_bfloat16  g_wflo[DD * DD];
__device__ __nv_bfloat16  g_w2hi[DD * DD];
__device__ __nv_bfloat16  g_w2lo[DD * DD];
__device__ float          g_c[DD];                    // c = Wf*bu
__device__ float          g_zero[DD];                 // stays zero (never written)
__device__ float          g_P[BB * SS];               // within-chunk prefix products of a_t
__device__ float          g_Be[NCH * NCD];            // chunk-end scan values
__device__ float          g_cin[NCH * NCD];           // chunk carry-ins

// ---------------------------------------------------------------------------
// PTX helpers (base-target only: cp.async / ldmatrix / mma.sync — no tcgen05,
// which requires the sm_103a '.a' target the harness's nvcc does not emit)
// ---------------------------------------------------------------------------
__device__ __forceinline__ uint32_t smem_u32(const void* p) {
    uint32_t a;
    asm("{ .reg .u64 t; cvta.to.shared.u64 t, %1; cvt.u32.u64 %0, t; }" : "=r"(a) : "l"(p));
    return a;
}
__device__ __forceinline__ void cp16(uint32_t dst, const void* src) {
    asm volatile("cp.async.cg.shared.global [%0], [%1], 16;" :: "r"(dst), "l"(src));
}
__device__ __forceinline__ void cp_commit() {
    asm volatile("cp.async.commit_group;" ::: "memory");
}
template<int N>
__device__ __forceinline__ void cp_wait() {
    asm volatile("cp.async.wait_group %0;" :: "n"(N) : "memory");
}
__device__ __forceinline__ void ldm_x4(uint32_t* r, uint32_t addr) {
    asm volatile("ldmatrix.sync.aligned.m8n8.x4.shared.b16 {%0,%1,%2,%3}, [%4];"
                 : "=r"(r[0]), "=r"(r[1]), "=r"(r[2]), "=r"(r[3]) : "r"(addr));
}
__device__ __forceinline__ void mma16816(float* d, const uint32_t* a, const uint32_t* b) {
    asm volatile(
        "mma.sync.aligned.m16n8k16.row.col.f32.bf16.bf16.f32 "
        "{%0,%1,%2,%3}, {%4,%5,%6,%7}, {%8,%9}, {%0,%1,%2,%3};"
        : "+f"(d[0]), "+f"(d[1]), "+f"(d[2]), "+f"(d[3])
        : "r"(a[0]), "r"(a[1]), "r"(a[2]), "r"(a[3]), "r"(b[0]), "r"(b[1]));
}
__device__ __forceinline__ uint32_t pack_bf16x2(float a, float b) {
    __nv_bfloat162 h(__float2bfloat16_rn(a), __float2bfloat16_rn(b));
    return *reinterpret_cast<uint32_t*>(&h);
}
__device__ __forceinline__ float get_decay(const float* decay_p) {
    return 1.0f / (1.0f + expf(-decay_p[0]));
}

#define BN 128
#define BKK 32
#define ASTR 40                       // 32 + 8 pad bf16 -> 80B rows, conflict-free
#define TILE80 (128 * 80)             // 10240 B: one padded bf16 tile (128 rows)
#define NKB (DD / BKK)                // 32

// ---------------------------------------------------------------------------
// Big fused GEMM + chunk-scan epilogue.
//   compute y = x*W2^T + c (x hi/lo split done in-smem),
//   then within-chunk zero-init scan of m*y along the 128 rows (= s-chunk),
//   write scan result to Y and the chunk-end value to Be.
// CTA tile 128x128, 8 warps (4x2), warp tile 32x64.
// ---------------------------------------------------------------------------
#define RAW_B 16384
#define OFF_RAW 0
#define OFF_ACV (2 * RAW_B)                   // 32768
#define OFF_B   (OFF_ACV + 2 * TILE80)        // 53248
#define FUSED_SMEM (OFF_B + 2 * 2 * TILE80)   // 94208  (>= 128*132*4 = 67584)
#define YSTR 132                               // padded fp32 row stride for scan tile

__global__ __launch_bounds__(256, 2)
void gemm_xf32(const float* __restrict__ X,
               const __nv_bfloat16* __restrict__ Bhi,
               const __nv_bfloat16* __restrict__ Blo,
               const float* __restrict__ bias,
               const float* __restrict__ mask,
               const float* __restrict__ decay_p,
               float* __restrict__ Y,
               float* __restrict__ Be)
{
    extern __shared__ __align__(16) char smem[];
    const uint32_t sb = smem_u32(smem);

    const int tid  = threadIdx.x;
    const int wid  = tid >> 5;
    const int lane = tid & 31;
    const int wm   = wid & 3;    // warp row (M)
    const int wn   = wid >> 2;   // warp col (N)
    const int bx   = blockIdx.x; // N tile
    const int by   = blockIdx.y; // M tile == (b, chunk)

    // B loader
    const int r0  = tid >> 2;
    const int c16 = tid & 3;
    const __nv_bfloat16* Bh0 = Bhi + (size_t)(bx * BN + r0) * DD + c16 * 8;
    const __nv_bfloat16* Bl0 = Blo + (size_t)(bx * BN + r0) * DD + c16 * 8;
    const uint32_t dstb = (uint32_t)(r0 * 80 + c16 * 16);

    // convert mapping
    const int cv_row  = tid >> 1;
    const int cv_half = tid & 1;

    // ldmatrix addressing
    const int a_row = (lane & 7) + ((lane >> 3) & 1) * 8;
    const int a_col = (lane >> 4) * 8;
    const int b_row = (lane & 7) + (lane >> 4) * 8;
    const int b_col = ((lane >> 3) & 1) * 8;

    float acc[2][8][4];
    #pragma unroll
    for (int i = 0; i < 2; i++)
        #pragma unroll
        for (int j = 0; j < 8; j++)
            #pragma unroll
            for (int q = 0; q < 4; q++)
                acc[i][j][q] = 0.0f;

    auto issue = [&](int kb, int st) {
        const int ko = kb * BKK;
        const uint32_t rawst = sb + OFF_RAW + st * RAW_B;
        #pragma unroll
        for (int j = 0; j < 4; j++) {
            const int u = tid + j * 256;
            const int row = u >> 3;
            const int cc  = u & 7;
            cp16(rawst + row * 128 + cc * 16,
                 X + (size_t)(by * 128 + row) * DD + ko + cc * 4);
        }
        const uint32_t bst = sb + OFF_B + st * (2 * TILE80);
        #pragma unroll
        for (int j = 0; j < 2; j++) {
            const size_t ro = (size_t)j * 64 * DD;
            const uint32_t so = (uint32_t)(j * 64 * 80);
            cp16(bst + dstb + so, Bh0 + ro + ko);
            cp16(bst + TILE80 + dstb + so, Bl0 + ro + ko);
        }
        cp_commit();
    };

    issue(0, 0);

    for (int kb = 0; kb < NKB; kb++) {
        const int st = kb & 1;
        cp_wait<0>();
        __syncthreads();
        if (kb + 1 < NKB) issue(kb + 1, st ^ 1);

        // in-smem split: raw fp32 -> Acvt hi/lo bf16 (padded)
        {
            const char* src = smem + OFF_RAW + st * RAW_B + cv_row * 128 + cv_half * 64;
            float f[16];
            #pragma unroll
            for (int i = 0; i < 4; i++) {
                const float4 v = *(const float4*)(src + i * 16);
                f[4*i+0] = v.x; f[4*i+1] = v.y; f[4*i+2] = v.z; f[4*i+3] = v.w;
            }
            uint32_t h[8], l[8];
            #pragma unroll
            for (int i = 0; i < 8; i++) {
                const float fa = f[2*i], fbv = f[2*i+1];
                h[i] = pack_bf16x2(fa, fbv);
                const float ra = fa - __bfloat162float(__float2bfloat16_rn(fa));
                const float rb = fbv - __bfloat162float(__float2bfloat16_rn(fbv));
                l[i] = pack_bf16x2(ra, rb);
            }
            const uint32_t dsth = sb + OFF_ACV + cv_row * 80 + cv_half * 32;
            const uint32_t dstl = dsth + TILE80;
            asm volatile("st.shared.v4.b32 [%0], {%1,%2,%3,%4};"
                         :: "r"(dsth), "r"(h[0]), "r"(h[1]), "r"(h[2]), "r"(h[3]) : "memory");
            asm volatile("st.shared.v4.b32 [%0], {%1,%2,%3,%4};"
                         :: "r"(dsth + 16), "r"(h[4]), "r"(h[5]), "r"(h[6]), "r"(h[7]) : "memory");
            asm volatile("st.shared.v4.b32 [%0], {%1,%2,%3,%4};"
                         :: "r"(dstl), "r"(l[0]), "r"(l[1]), "r"(l[2]), "r"(l[3]) : "memory");
            asm volatile("st.shared.v4.b32 [%0], {%1,%2,%3,%4};"
                         :: "r"(dstl + 16), "r"(l[4]), "r"(l[5]), "r"(l[6]), "r"(l[7]) : "memory");
        }
        __syncthreads();

        const uint32_t stgA = sb + OFF_ACV;
        const uint32_t stgB = sb + OFF_B + st * (2 * TILE80);
        #pragma unroll
        for (int ks = 0; ks < 2; ks++) {
            uint32_t aH[2][4], aL[2][4];
            #pragma unroll
            for (int mt = 0; mt < 2; mt++) {
                const uint32_t ra =
                    (uint32_t)(((wm * 32 + mt * 16 + a_row) * ASTR + ks * 16 + a_col) * 2);
                ldm_x4(aH[mt], stgA + ra);
                ldm_x4(aL[mt], stgA + TILE80 + ra);
            }
            #pragma unroll
            for (int g = 0; g < 4; g++) {
                const uint32_t rb =
                    (uint32_t)(((wn * 64 + g * 16 + b_row) * ASTR + ks * 16 + b_col) * 2);
                uint32_t bH[4], bL[4];
                ldm_x4(bH, stgB + rb);
                ldm_x4(bL, stgB + TILE80 + rb);
                #pragma unroll
                for (int mt = 0; mt < 2; mt++) {
                    mma16816(acc[mt][2 * g + 0], aH[mt], bH);
                    mma16816(acc[mt][2 * g + 1], aH[mt], bH + 2);
                    mma16816(acc[mt][2 * g + 0], aH[mt], bL);
                    mma16816(acc[mt][2 * g + 1], aH[mt], bL + 2);
                    mma16816(acc[mt][2 * g + 0], aL[mt], bH);
                    mma16816(acc[mt][2 * g + 1], aL[mt], bH + 2);
                }
            }
        }
    }

    // ---- epilogue: stage y(+bias) to smem, chunk-scan, write scan + Be ----
    __syncthreads();   // mainloop smem reads done; reuse smem as fp32 tile
    {
        const int rb0 = wm * 32 + (lane >> 2);
        const int cb  = wn * 64 + (lane & 3) * 2;
        #pragma unroll
        for (int mt = 0; mt < 2; mt++) {
            #pragma unroll
            for (int nt = 0; nt < 8; nt++) {
                const int c = cb + nt * 8;
                const float2 bv = *(const float2*)(bias + bx * BN + c);
                float* p0 = (float*)(smem + ((rb0 + mt * 16) * YSTR + c) * 4);
                float* p1 = (float*)(smem + ((rb0 + mt * 16 + 8) * YSTR + c) * 4);
                p0[0] = acc[mt][nt][0] + bv.x;
                p0[1] = acc[mt][nt][1] + bv.y;
                p1[0] = acc[mt][nt][2] + bv.x;
                p1[1] = acc[mt][nt][3] + bv.y;
            }
        }
    }
    __syncthreads();

    const int bb = by >> 5;          // batch
    const int ch = by & 31;          // chunk
    if (tid < 128) {
        const float decay = get_decay(decay_p);
        const float* mrow = mask + (size_t)bb * SS + ch * CHS;
        float* col = (float*)(smem) + tid;
        float val = 0.0f;
        for (int s = 0; s < CHS; s += 8) {
            float mv[8], yv[8];
            #pragma unroll
            for (int i = 0; i < 8; i++) {
                mv[i] = mrow[s + i];
                yv[i] = col[(s + i) * YSTR];
            }
            #pragma unroll
            for (int i = 0; i < 8; i++) {
                const float a = mv[i] * decay + (1.0f - mv[i]);
                val = fmaf(a, val, mv[i] * yv[i]);
                col[(s + i) * YSTR] = val;
            }
        }
        Be[ch * NCD + bb * DD + bx * BN + tid] = val;
    }
    __syncthreads();

    // coalesced write of the scanned tile to Y
    #pragma unroll
    for (int j = 0; j < 16; j++) {
        const int u  = tid + j * 256;
        const int rw = u >> 5;
        const int c4 = (u & 31) * 4;
        const float4 v = *(const float4*)(smem + (rw * YSTR + c4) * 4);
        *(float4*)(Y + (size_t)(by * 128 + rw) * DD + bx * BN + c4) = v;
    }
}

// ---------------------------------------------------------------------------
// Small split-bf16 GEMM (pre-split operands) for W2 = Wf*Wu. M tile 64.
// ---------------------------------------------------------------------------
#define SM1_STAGE (2 * 64 * 80 + 2 * TILE80)
#define SM1_SMEM  (2 * SM1_STAGE)

__global__ __launch_bounds__(256, 2)
void gemm_w2(const __nv_bfloat16* __restrict__ Ahi,
             const __nv_bfloat16* __restrict__ Alo,
             const __nv_bfloat16* __restrict__ Bhi,
             const __nv_bfloat16* __restrict__ Blo,
             const float* __restrict__ bias,
             float* __restrict__ C)
{
    constexpr int ATILE_B = 64 * 80;
    extern __shared__ __align__(16) char smem[];
    const uint32_t sb = smem_u32(smem);

    const int tid  = threadIdx.x;
    const int wid  = tid >> 5;
    const int lane = tid & 31;
    const int wm   = wid & 3;
    const int wn   = wid >> 2;
    const int bx   = blockIdx.x;
    const int by   = blockIdx.y;

    const int r0  = tid >> 2;    // 0..63
    const int c16 = tid & 3;
    const __nv_bfloat16* Ah0 = Ahi + (size_t)(by * 64 + r0) * DD + c16 * 8;
    const __nv_bfloat16* Al0 = Alo + (size_t)(by * 64 + r0) * DD + c16 * 8;
    const __nv_bfloat16* Bh0 = Bhi + (size_t)(bx * BN + r0) * DD + c16 * 8;
    const __nv_bfloat16* Bl0 = Blo + (size_t)(bx * BN + r0) * DD + c16 * 8;
    const uint32_t dsta = (uint32_t)(r0 * 80 + c16 * 16);

    const int a_row = (lane & 7) + ((lane >> 3) & 1) * 8;
    const int a_col = (lane >> 4) * 8;
    const int b_row = (lane & 7) + (lane >> 4) * 8;
    const int b_col = ((lane >> 3) & 1) * 8;

    float acc[8][4];
    #pragma unroll
    for (int j = 0; j < 8; j++)
        #pragma unroll
        for (int q = 0; q < 4; q++)
            acc[j][q] = 0.0f;

    auto issue = [&](int kb, int st) {
        const uint32_t stg = sb + st * SM1_STAGE;
        const int ko = kb * BKK;
        cp16(stg + dsta, Ah0 + ko);
        cp16(stg + ATILE_B + dsta, Al0 + ko);
        #pragma unroll
        for (int j = 0; j < 2; j++) {
            const size_t ro = (size_t)j * 64 * DD;
            const uint32_t so = (uint32_t)(j * 64 * 80);
            cp16(stg + 2 * ATILE_B + dsta + so, Bh0 + ro + ko);
            cp16(stg + 2 * ATILE_B + TILE80 + dsta + so, Bl0 + ro + ko);
        }
        cp_commit();
    };

    issue(0, 0);
    for (int kb = 0; kb < NKB; kb++) {
        const int st = kb & 1;
        cp_wait<0>();
        __syncthreads();
        if (kb + 1 < NKB) issue(kb + 1, st ^ 1);

        const uint32_t stg = sb + st * SM1_STAGE;
        #pragma unroll
        for (int ks = 0; ks < 2; ks++) {
            uint32_t aH[4], aL[4];
            const uint32_t ra = (uint32_t)(((wm * 16 + a_row) * ASTR + ks * 16 + a_col) * 2);
            ldm_x4(aH, stg + ra);
            ldm_x4(aL, stg + ATILE_B + ra);
            #pragma unroll
            for (int g = 0; g < 4; g++) {
                const uint32_t rb = (uint32_t)(((wn * 64 + g * 16 + b_row) * ASTR + ks * 16 + b_col) * 2);
                uint32_t bH[4], bL[4];
                ldm_x4(bH, stg + 2 * ATILE_B + rb);
                ldm_x4(bL, stg + 2 * ATILE_B + TILE80 + rb);
                mma16816(acc[2 * g + 0], aH, bH);
                mma16816(acc[2 * g + 1], aH, bH + 2);
                mma16816(acc[2 * g + 0], aH, bL);
                mma16816(acc[2 * g + 1], aH, bL + 2);
                mma16816(acc[2 * g + 0], aL, bH);
                mma16816(acc[2 * g + 1], aL, bH + 2);
            }
        }
    }

    const int crow = by * 64 + wm * 16 + (lane >> 2);
    const int ccol = bx * BN + wn * 64 + (lane & 3) * 2;
    #pragma unroll
    for (int nt = 0; nt < 8; nt++) {
        const int gn = ccol + nt * 8;
        const float2 bv = *(const float2*)(bias + gn);
        float2 o0, o1;
        o0.x = acc[nt][0] + bv.x;
        o0.y = acc[nt][1] + bv.y;
        o1.x = acc[nt][2] + bv.x;
        o1.y = acc[nt][3] + bv.y;
        *(float2*)(C + (size_t)crow * DD + gn)       = o0;
        *(float2*)(C + (size_t)(crow + 8) * DD + gn) = o1;
    }
}

// ---------------------------------------------------------------------------
// fp32 -> (hi, lo) bf16 split (weights only)
// ---------------------------------------------------------------------------
__global__ void split_kernel(const float* __restrict__ in,
                             __nv_bfloat16* __restrict__ hi,
                             __nv_bfloat16* __restrict__ lo, int n4)
{
    for (int i = blockIdx.x * blockDim.x + threadIdx.x; i < n4; i += gridDim.x * blockDim.x) {
        const float4 v = ((const float4*)in)[i];
        __nv_bfloat16 hx = __float2bfloat16_rn(v.x);
        __nv_bfloat16 hy = __float2bfloat16_rn(v.y);
        __nv_bfloat16 hz = __float2bfloat16_rn(v.z);
        __nv_bfloat16 hw = __float2bfloat16_rn(v.w);
        __nv_bfloat162* h2 = (__nv_bfloat162*)hi;
        __nv_bfloat162* l2 = (__nv_bfloat162*)lo;
        h2[2 * i + 0] = __nv_bfloat162(hx, hy);
        h2[2 * i + 1] = __nv_bfloat162(hz, hw);
        l2[2 * i + 0] = __nv_bfloat162(__float2bfloat16_rn(v.x - __bfloat162float(hx)),
                                       __float2bfloat16_rn(v.y - __bfloat162float(hy)));
        l2[2 * i + 1] = __nv_bfloat162(__float2bfloat16_rn(v.z - __bfloat162float(hz)),
                                       __float2bfloat16_rn(v.w - __bfloat162float(hw)));
    }
}

// ---------------------------------------------------------------------------
// 1024x1024 fp32 transpose (Wu -> Wu^T)
// ---------------------------------------------------------------------------
__global__ void transpose_k(const float* __restrict__ in, float* __restrict__ out)
{
    __shared__ float t[32][33];
    const int x  = blockIdx.x * 32 + threadIdx.x;
    const int y0 = blockIdx.y * 32 + threadIdx.y;
    #pragma unroll
    for (int j = 0; j < 4; j++)
        t[threadIdx.y + j * 8][threadIdx.x] = in[(size_t)(y0 + j * 8) * DD + x];
    __syncthreads();
    const int x2 = blockIdx.y * 32 + threadIdx.x;
    const int y2 = blockIdx.x * 32 + threadIdx.y;
    #pragma unroll
    for (int j = 0; j < 4; j++)
        out[(size_t)(y2 + j * 8) * DD + x2] = t[threadIdx.x][threadIdx.y + j * 8];
}

// ---------------------------------------------------------------------------
// c[e] = sum_d Wf[e,d] * bu[d]
// ---------------------------------------------------------------------------
__global__ void bias_proj(const float* __restrict__ Wf,
                          const float* __restrict__ bu,
                          float* __restrict__ c)
{
    __shared__ float red[8];
    const int e = blockIdx.x;
    float s = 0.0f;
    for (int d = threadIdx.x; d < DD; d += 256)
        s += Wf[(size_t)e * DD + d] * bu[d];
    #pragma unroll
    for (int o = 16; o > 0; o >>= 1)
        s += __shfl_down_sync(0xffffffffu, s, o);
    if ((threadIdx.x & 31) == 0) red[threadIdx.x >> 5] = s;
    __syncthreads();
    if (threadIdx.x == 0) {
        float t = 0.0f;
        #pragma unroll
        for (int w = 0; w < 8; w++) t += red[w];
        c[e] = t;
    }
}

// ---------------------------------------------------------------------------
// Per-(b,chunk) prefix products of a_t within chunk: P[b*SS + ch*CHS + s]
// One thread per (b, ch): 256 threads.
// ---------------------------------------------------------------------------
__global__ void prefix_kernel(const float* __restrict__ mask,
                              const float* __restrict__ decay_p,
                              float* __restrict__ P)
{
    const int g = threadIdx.x;          // 0..255
    if (g >= BB * NCH) return;
    const int b  = g >> 5;
    const int ch = g & 31;
    const float decay = get_decay(decay_p);
    const float* mrow = mask + (size_t)b * SS + ch * CHS;
    float* prow = P + (size_t)b * SS + ch * CHS;
    float A = 1.0f;
    for (int s = 0; s < CHS; s++) {
        const float m = mrow[s];
        A *= m * decay + (1.0f - m);
        prow[s] = A;
    }
}

// ---------------------------------------------------------------------------
// combine: chain chunk summaries per (b,d). A_ch = P at chunk end.
// ---------------------------------------------------------------------------
__global__ void scan_combine(const float* __restrict__ P,
                             const float* __restrict__ Be,
                             float* __restrict__ cin)
{
    const int g = blockIdx.x * blockDim.x + threadIdx.x;   // 0..8191 = b*DD+d
    const int b = g >> 10;
    float carry = 0.0f;
    #pragma unroll
    for (int ch = 0; ch < NCH; ch++) {
        cin[ch * NCD + g] = carry;
        const float A = P[(size_t)b * SS + ch * CHS + (CHS - 1)];
        carry = fmaf(A, carry, Be[ch * NCD + g]);
    }
}

// ---------------------------------------------------------------------------
// pass2 (fully parallel streaming): out = yscan + P_t * cin + bf
// ---------------------------------------------------------------------------
__global__ void scan_finish(const float* __restrict__ Y,
                            const float* __restrict__ P,
                            const float* __restrict__ cin,
                            const float* __restrict__ bf,
                            float* __restrict__ out)
{
    const int n4 = MTOT * DD / 4;
    for (int i = blockIdx.x * blockDim.x + threadIdx.x; i < n4; i += gridDim.x * blockDim.x) {
        const int m  = i >> 8;            // row (b*SS + s)
        const int d  = (i & 255) * 4;
        const int b  = m >> 12;
        const int s  = m & (SS - 1);
        const int ch = s >> 7;
        const float p = P[(size_t)b * SS + s];
        const float4 yv = *(const float4*)(Y + (size_t)m * DD + d);
        const float4 cv = *(const float4*)(cin + ch * NCD + b * DD + d);
        const float4 bv = *(const float4*)(bf + d);
        float4 o;
        o.x = fmaf(p, cv.x, yv.x) + bv.x;
        o.y = fmaf(p, cv.y, yv.y) + bv.y;
        o.z = fmaf(p, cv.z, yv.z) + bv.z;
        o.w = fmaf(p, cv.w, yv.w) + bv.w;
        *(float4*)(out + (size_t)m * DD + d) = o;
    }
}

// ---------------------------------------------------------------------------
// kernel_launch
// Inputs: 0:x (B,S,D)  1:mask (B,S)  2:Wu (D,D)  3:bu (D)
//         4:Wf (D,D)   5:bf (D)      6:decay_param (1)
//
// Math: out = scan(m*(x*Wu^T + bu))*Wf^T + bf == scan(m*(x*W2^T + c)) + bf
//       with W2 = Wf*Wu, c = Wf*bu. Chunked scan:
//       mem_t = scan0_t + P_t*cin  (within-chunk zero-init scan computed in
//       the GEMM epilogue; P = prefix products; cin via chunk combine).
// ---------------------------------------------------------------------------
extern "C" void kernel_launch(void* const* d_in, const int* in_sizes, int n_in,
                              void* d_out, int out_size)
{
    const float* x     = (const float*)d_in[0];
    const float* mask  = (const float*)d_in[1];
    const float* Wu    = (const float*)d_in[2];
    const float* bu    = (const float*)d_in[3];
    const float* Wf    = (const float*)d_in[4];
    const float* bf    = (const float*)d_in[5];
    const float* decay = (const float*)d_in[6];
    float* out = (float*)d_out;

    float *y, *wut, *w2, *cvec, *zero, *P, *Be, *cin;
    __nv_bfloat16 *wuthi, *wutlo, *wfhi, *wflo, *w2hi, *w2lo;
    cudaGetSymbolAddress((void**)&y,     g_y);
    cudaGetSymbolAddress((void**)&wut,   g_wut);
    cudaGetSymbolAddress((void**)&w2,    g_w2);
    cudaGetSymbolAddress((void**)&wuthi, g_wuthi);
    cudaGetSymbolAddress((void**)&wutlo, g_wutlo);
    cudaGetSymbolAddress((void**)&wfhi,  g_wfhi);
    cudaGetSymbolAddress((void**)&wflo,  g_wflo);
    cudaGetSymbolAddress((void**)&w2hi,  g_w2hi);
    cudaGetSymbolAddress((void**)&w2lo,  g_w2lo);
    cudaGetSymbolAddress((void**)&cvec,  g_c);
    cudaGetSymbolAddress((void**)&zero,  g_zero);
    cudaGetSymbolAddress((void**)&P,     g_P);
    cudaGetSymbolAddress((void**)&Be,    g_Be);
    cudaGetSymbolAddress((void**)&cin,   g_cin);

    cudaFuncSetAttribute(gemm_xf32, cudaFuncAttributeMaxDynamicSharedMemorySize, FUSED_SMEM);
    cudaFuncSetAttribute(gemm_w2,   cudaFuncAttributeMaxDynamicSharedMemorySize, SM1_SMEM);

    // --- weight prep + prefix products (small) ---
    transpose_k<<<dim3(32, 32), dim3(32, 8)>>>(Wu, wut);          // Wu^T
    split_kernel<<<128, 256>>>(wut, wuthi, wutlo, DD * DD / 4);
    split_kernel<<<128, 256>>>(Wf,  wfhi,  wflo,  DD * DD / 4);
    bias_proj<<<DD, 256>>>(Wf, bu, cvec);                         // c = Wf*bu
    prefix_kernel<<<1, 256>>>(mask, decay, P);

    // W2 = Wf * Wu
    gemm_w2<<<dim3(DD / BN, 1024 / 64), 256, SM1_SMEM>>>(
        wfhi, wflo, wuthi, wutlo, zero, w2);
    split_kernel<<<128, 256>>>(w2, w2hi, w2lo, DD * DD / 4);

    // --- big path: y = x*W2^T + c, then within-chunk scan, all in one kernel
    gemm_xf32<<<dim3(DD / BN, MTOT / 128), 256, FUSED_SMEM>>>(
        x, w2hi, w2lo, cvec, mask, decay, y, Be);

    // chunk combine + fully-parallel finish
    scan_combine<<<NCD / 256, 256>>>(P, Be, cin);
    scan_finish<<<4096, 256>>>(y, P, cin, bf, out);
}

// round 15
// speedup vs baseline: 4.9292x; 1.0964x over previous
#include <cuda_runtime.h>
#include <cuda_bf16.h>
#include <math.h>
#include <stdint.h>

// Problem constants (fixed by the dataset)
#define BB 8
#define SS 4096
#define DD 1024
#define MTOT (BB * SS)   // 32768

#define NCH 32
#define CHS (SS / NCH)   // 128 steps per chunk == GEMM M-tile
#define NCD (BB * DD)    // 8192 chains

// ---------------------------------------------------------------------------
// Scratch (device globals; no allocation allowed). Zero-initialized at load.
// ---------------------------------------------------------------------------
__device__ float          g_y[(size_t)MTOT * DD];     // within-chunk zero-init scan
__device__ float          g_w2[DD * DD];              // W2 = Wf*Wu (fp32)
__device__ __nv_bfloat16  g_wuthi[DD * DD];           // Wu^T hi/lo
__device__ __nv_bfloat16  g_wutlo[DD * DD];
__device__ __nv_bfloat16  g_wfhi[DD * DD];
__device__ __nv_bfloat16  g_wflo[DD * DD];
__device__ __nv_bfloat16  g_w2hi[DD * DD];
__device__ __nv_bfloat16  g_w2lo[DD * DD];
__device__ float          g_c[DD];                    // c = Wf*bu
__device__ float          g_zero[DD];                 // stays zero (never written)
__device__ float          g_P[BB * SS];               // within-chunk prefix products
__device__ float          g_Be[NCH * NCD];            // chunk-end scan values
__device__ float          g_cin[NCH * NCD];           // chunk carry-ins

// ---------------------------------------------------------------------------
// PTX helpers (base-target only; tcgen05 needs the '.a' target the harness
// nvcc does not emit)
// ---------------------------------------------------------------------------
__device__ __forceinline__ uint32_t smem_u32(const void* p) {
    uint32_t a;
    asm("{ .reg .u64 t; cvta.to.shared.u64 t, %1; cvt.u32.u64 %0, t; }" : "=r"(a) : "l"(p));
    return a;
}
__device__ __forceinline__ void cp16(uint32_t dst, const void* src) {
    asm volatile("cp.async.cg.shared.global [%0], [%1], 16;" :: "r"(dst), "l"(src));
}
__device__ __forceinline__ void cp_commit() {
    asm volatile("cp.async.commit_group;" ::: "memory");
}
template<int N>
__device__ __forceinline__ void cp_wait() {
    asm volatile("cp.async.wait_group %0;" :: "n"(N) : "memory");
}
__device__ __forceinline__ void ldm_x4(uint32_t* r, uint32_t addr) {
    asm volatile("ldmatrix.sync.aligned.m8n8.x4.shared.b16 {%0,%1,%2,%3}, [%4];"
                 : "=r"(r[0]), "=r"(r[1]), "=r"(r[2]), "=r"(r[3]) : "r"(addr));
}
__device__ __forceinline__ void mma16816(float* d, const uint32_t* a, const uint32_t* b) {
    asm volatile(
        "mma.sync.aligned.m16n8k16.row.col.f32.bf16.bf16.f32 "
        "{%0,%1,%2,%3}, {%4,%5,%6,%7}, {%8,%9}, {%0,%1,%2,%3};"
        : "+f"(d[0]), "+f"(d[1]), "+f"(d[2]), "+f"(d[3])
        : "r"(a[0]), "r"(a[1]), "r"(a[2]), "r"(a[3]), "r"(b[0]), "r"(b[1]));
}
__device__ __forceinline__ uint32_t pack_bf16x2(float a, float b) {
    __nv_bfloat162 h(__float2bfloat16_rn(a), __float2bfloat16_rn(b));
    return *reinterpret_cast<uint32_t*>(&h);
}
__device__ __forceinline__ float get_decay(const float* decay_p) {
    return 1.0f / (1.0f + expf(-decay_p[0]));
}

#define BN 128
#define BKK 32
#define ASTR 40                       // 32 + 8 pad bf16 -> 80B rows, conflict-free
#define TILE80 (128 * 80)             // 10240 B: one padded bf16 tile (128 rows)
#define NKB (DD / BKK)                // 32

// ---------------------------------------------------------------------------
// Big fused GEMM + chunk-scan epilogue, single-barrier pipelined mainloop.
//   y = x*W2^T + c  (x split to hi/lo bf16 in-smem, owner-computes: each
//   thread converts exactly the chunks it cp.async'd -> no barrier needed
//   between load and convert), then within-chunk zero-init scan of m*y.
// CTA tile 128x128, 8 warps (4x2), warp tile 32x64.
// smem: raw[2]*16KB + Acvt(hi+lo)[2]*20KB + B(hi+lo)[2]*20KB = 112KB, 2 CTA/SM.
// ---------------------------------------------------------------------------
#define RAW_B 16384
#define OFF_RAW 0
#define ACV_STAGE (2 * TILE80)                // 20480 (hi + lo)
#define OFF_ACV (2 * RAW_B)                   // 32768
#define OFF_B   (OFF_ACV + 2 * ACV_STAGE)     // 73728
#define FUSED_SMEM (OFF_B + 2 * 2 * TILE80)   // 114688
#define YSTR 132                              // padded fp32 row stride (epilogue)

__global__ __launch_bounds__(256, 2)
void gemm_xf32(const float* __restrict__ X,
               const __nv_bfloat16* __restrict__ Bhi,
               const __nv_bfloat16* __restrict__ Blo,
               const float* __restrict__ bias,
               const float* __restrict__ mask,
               const float* __restrict__ decay_p,
               float* __restrict__ Y,
               float* __restrict__ Be)
{
    extern __shared__ __align__(16) char smem[];
    const uint32_t sb = smem_u32(smem);

    const int tid  = threadIdx.x;
    const int wid  = tid >> 5;
    const int lane = tid & 31;
    const int wm   = wid & 3;    // warp row (M)
    const int wn   = wid >> 2;   // warp col (N)
    const int bx   = blockIdx.x; // N tile
    const int by   = blockIdx.y; // M tile == (b, chunk)

    // B loader
    const int r0  = tid >> 2;
    const int c16 = tid & 3;
    const __nv_bfloat16* Bh0 = Bhi + (size_t)(bx * BN + r0) * DD + c16 * 8;
    const __nv_bfloat16* Bl0 = Blo + (size_t)(bx * BN + r0) * DD + c16 * 8;
    const uint32_t dstb = (uint32_t)(r0 * 80 + c16 * 16);

    // ldmatrix addressing
    const int a_row = (lane & 7) + ((lane >> 3) & 1) * 8;
    const int a_col = (lane >> 4) * 8;
    const int b_row = (lane & 7) + (lane >> 4) * 8;
    const int b_col = ((lane >> 3) & 1) * 8;

    float acc[2][8][4];
    #pragma unroll
    for (int i = 0; i < 2; i++)
        #pragma unroll
        for (int j = 0; j < 8; j++)
            #pragma unroll
            for (int q = 0; q < 4; q++)
                acc[i][j][q] = 0.0f;

    // owner-computes: thread owns raw chunks u = tid + j*256 (row u>>3, 16B col u&7)
    auto issue_raw = [&](int kb, int st) {
        const int ko = kb * BKK;
        const uint32_t rawst = sb + OFF_RAW + st * RAW_B;
        #pragma unroll
        for (int j = 0; j < 4; j++) {
            const int u = tid + j * 256;
            const int row = u >> 3;
            const int cc  = u & 7;
            cp16(rawst + row * 128 + cc * 16,
                 X + (size_t)(by * 128 + row) * DD + ko + cc * 4);
        }
        cp_commit();
    };
    auto issue_B = [&](int kb, int st) {
        const int ko = kb * BKK;
        const uint32_t bst = sb + OFF_B + st * (2 * TILE80);
        #pragma unroll
        for (int j = 0; j < 2; j++) {
            const size_t ro = (size_t)j * 64 * DD;
            const uint32_t so = (uint32_t)(j * 64 * 80);
            cp16(bst + dstb + so, Bh0 + ro + ko);
            cp16(bst + TILE80 + dstb + so, Bl0 + ro + ko);
        }
        cp_commit();
    };
    // convert OWN chunks: raw[st] -> Acvt[st] hi/lo (no barrier needed)
    auto convert = [&](int st) {
        const uint32_t rawst = sb + OFF_RAW + st * RAW_B;
        const uint32_t acvst = sb + OFF_ACV + st * ACV_STAGE;
        #pragma unroll
        for (int j = 0; j < 4; j++) {
            const int u = tid + j * 256;
            const int row = u >> 3;
            const int cc  = u & 7;
            float4 v;
            asm volatile("ld.shared.v4.f32 {%0,%1,%2,%3}, [%4];"
                         : "=f"(v.x), "=f"(v.y), "=f"(v.z), "=f"(v.w)
                         : "r"(rawst + row * 128 + cc * 16));
            const uint32_t h0 = pack_bf16x2(v.x, v.y);
            const uint32_t h1 = pack_bf16x2(v.z, v.w);
            const float lx = v.x - __bfloat162float(__float2bfloat16_rn(v.x));
            const float ly = v.y - __bfloat162float(__float2bfloat16_rn(v.y));
            const float lz = v.z - __bfloat162float(__float2bfloat16_rn(v.z));
            const float lw = v.w - __bfloat162float(__float2bfloat16_rn(v.w));
            const uint32_t l0 = pack_bf16x2(lx, ly);
            const uint32_t l1 = pack_bf16x2(lz, lw);
            const uint32_t da = acvst + row * 80 + cc * 8;
            asm volatile("st.shared.v2.b32 [%0], {%1,%2};"
                         :: "r"(da), "r"(h0), "r"(h1) : "memory");
            asm volatile("st.shared.v2.b32 [%0], {%1,%2};"
                         :: "r"(da + TILE80), "r"(l0), "r"(l1) : "memory");
        }
    };

    // ---- prologue ----
    issue_raw(0, 0);            // group: raw0
    cp_wait<0>();
    convert(0);                 // own data -> Acvt0
    issue_B(0, 0);              // group: B0

    // ---- mainloop: ONE barrier per k-block ----
    for (int kb = 0; kb < NKB; kb++) {
        const int st = kb & 1;
        cp_wait<0>();           // B(kb) landed (own copies)
        __syncthreads();        // B(kb) + Acvt(kb) visible block-wide
        if (kb + 1 < NKB) {
            issue_raw(kb + 1, st ^ 1);   // group: raw(kb+1)
            issue_B(kb + 1, st ^ 1);     // group: B(kb+1)
        }

        const uint32_t stgA = sb + OFF_ACV + st * ACV_STAGE;
        const uint32_t stgB = sb + OFF_B + st * (2 * TILE80);
        #pragma unroll
        for (int ks = 0; ks < 2; ks++) {
            uint32_t aH[2][4], aL[2][4];
            #pragma unroll
            for (int mt = 0; mt < 2; mt++) {
                const uint32_t ra =
                    (uint32_t)(((wm * 32 + mt * 16 + a_row) * ASTR + ks * 16 + a_col) * 2);
                ldm_x4(aH[mt], stgA + ra);
                ldm_x4(aL[mt], stgA + TILE80 + ra);
            }
            #pragma unroll
            for (int g = 0; g < 4; g++) {
                const uint32_t rb =
                    (uint32_t)(((wn * 64 + g * 16 + b_row) * ASTR + ks * 16 + b_col) * 2);
                uint32_t bH[4], bL[4];
                ldm_x4(bH, stgB + rb);
                ldm_x4(bL, stgB + TILE80 + rb);
                #pragma unroll
                for (int mt = 0; mt < 2; mt++) {
                    mma16816(acc[mt][2 * g + 0], aH[mt], bH);
                    mma16816(acc[mt][2 * g + 1], aH[mt], bH + 2);
                    mma16816(acc[mt][2 * g + 0], aH[mt], bL);
                    mma16816(acc[mt][2 * g + 1], aH[mt], bL + 2);
                    mma16816(acc[mt][2 * g + 0], aL[mt], bH);
                    mma16816(acc[mt][2 * g + 1], aL[mt], bH + 2);
                }
            }
        }

        if (kb + 1 < NKB) {
            cp_wait<1>();        // raw(kb+1) done (B(kb+1) may be in flight)
            convert(st ^ 1);     // own data -> Acvt(kb+1); read after next sync
        }
    }

    // ---- epilogue: stage y(+bias) to smem, chunk-scan, write scan + Be ----
    __syncthreads();   // all smem reads of the mainloop done; reuse as fp32 tile
    {
        const int rb0 = wm * 32 + (lane >> 2);
        const int cb  = wn * 64 + (lane & 3) * 2;
        #pragma unroll
        for (int mt = 0; mt < 2; mt++) {
            #pragma unroll
            for (int nt = 0; nt < 8; nt++) {
                const int c = cb + nt * 8;
                const float2 bv = *(const float2*)(bias + bx * BN + c);
                float* p0 = (float*)(smem + ((rb0 + mt * 16) * YSTR + c) * 4);
                float* p1 = (float*)(smem + ((rb0 + mt * 16 + 8) * YSTR + c) * 4);
                p0[0] = acc[mt][nt][0] + bv.x;
                p0[1] = acc[mt][nt][1] + bv.y;
                p1[0] = acc[mt][nt][2] + bv.x;
                p1[1] = acc[mt][nt][3] + bv.y;
            }
        }
    }
    __syncthreads();

    const int bb = by >> 5;          // batch
    const int ch = by & 31;          // chunk
    if (tid < 128) {
        const float decay = get_decay(decay_p);
        const float* mrow = mask + (size_t)bb * SS + ch * CHS;
        float* col = (float*)(smem) + tid;
        float val = 0.0f;
        for (int s = 0; s < CHS; s += 8) {
            float mv[8], yv[8];
            #pragma unroll
            for (int i = 0; i < 8; i++) {
                mv[i] = mrow[s + i];
                yv[i] = col[(s + i) * YSTR];
            }
            #pragma unroll
            for (int i = 0; i < 8; i++) {
                const float a = mv[i] * decay + (1.0f - mv[i]);
                val = fmaf(a, val, mv[i] * yv[i]);
                col[(s + i) * YSTR] = val;
            }
        }
        Be[ch * NCD + bb * DD + bx * BN + tid] = val;
    }
    __syncthreads();

    // coalesced write of the scanned tile to Y
    #pragma unroll
    for (int j = 0; j < 16; j++) {
        const int u  = tid + j * 256;
        const int rw = u >> 5;
        const int c4 = (u & 31) * 4;
        const float4 v = *(const float4*)(smem + (rw * YSTR + c4) * 4);
        *(float4*)(Y + (size_t)(by * 128 + rw) * DD + bx * BN + c4) = v;
    }
}

// ---------------------------------------------------------------------------
// Small split-bf16 GEMM (pre-split operands) for W2 = Wf*Wu. M tile 64.
// ---------------------------------------------------------------------------
#define SM1_STAGE (2 * 64 * 80 + 2 * TILE80)
#define SM1_SMEM  (2 * SM1_STAGE)

__global__ __launch_bounds__(256, 2)
void gemm_w2(const __nv_bfloat16* __restrict__ Ahi,
             const __nv_bfloat16* __restrict__ Alo,
             const __nv_bfloat16* __restrict__ Bhi,
             const __nv_bfloat16* __restrict__ Blo,
             const float* __restrict__ bias,
             float* __restrict__ C)
{
    constexpr int ATILE_B = 64 * 80;
    extern __shared__ __align__(16) char smem[];
    const uint32_t sb = smem_u32(smem);

    const int tid  = threadIdx.x;
    const int wid  = tid >> 5;
    const int lane = tid & 31;
    const int wm   = wid & 3;
    const int wn   = wid >> 2;
    const int bx   = blockIdx.x;
    const int by   = blockIdx.y;

    const int r0  = tid >> 2;    // 0..63
    const int c16 = tid & 3;
    const __nv_bfloat16* Ah0 = Ahi + (size_t)(by * 64 + r0) * DD + c16 * 8;
    const __nv_bfloat16* Al0 = Alo + (size_t)(by * 64 + r0) * DD + c16 * 8;
    const __nv_bfloat16* Bh0 = Bhi + (size_t)(bx * BN + r0) * DD + c16 * 8;
    const __nv_bfloat16* Bl0 = Blo + (size_t)(bx * BN + r0) * DD + c16 * 8;
    const uint32_t dsta = (uint32_t)(r0 * 80 + c16 * 16);

    const int a_row = (lane & 7) + ((lane >> 3) & 1) * 8;
    const int a_col = (lane >> 4) * 8;
    const int b_row = (lane & 7) + (lane >> 4) * 8;
    const int b_col = ((lane >> 3) & 1) * 8;

    float acc[8][4];
    #pragma unroll
    for (int j = 0; j < 8; j++)
        #pragma unroll
        for (int q = 0; q < 4; q++)
            acc[j][q] = 0.0f;

    auto issue = [&](int kb, int st) {
        const uint32_t stg = sb + st * SM1_STAGE;
        const int ko = kb * BKK;
        cp16(stg + dsta, Ah0 + ko);
        cp16(stg + ATILE_B + dsta, Al0 + ko);
        #pragma unroll
        for (int j = 0; j < 2; j++) {
            const size_t ro = (size_t)j * 64 * DD;
            const uint32_t so = (uint32_t)(j * 64 * 80);
            cp16(stg + 2 * ATILE_B + dsta + so, Bh0 + ro + ko);
            cp16(stg + 2 * ATILE_B + TILE80 + dsta + so, Bl0 + ro + ko);
        }
        cp_commit();
    };

    issue(0, 0);
    for (int kb = 0; kb < NKB; kb++) {
        const int st = kb & 1;
        cp_wait<0>();
        __syncthreads();
        if (kb + 1 < NKB) issue(kb + 1, st ^ 1);

        const uint32_t stg = sb + st * SM1_STAGE;
        #pragma unroll
        for (int ks = 0; ks < 2; ks++) {
            uint32_t aH[4], aL[4];
            const uint32_t ra = (uint32_t)(((wm * 16 + a_row) * ASTR + ks * 16 + a_col) * 2);
            ldm_x4(aH, stg + ra);
            ldm_x4(aL, stg + ATILE_B + ra);
            #pragma unroll
            for (int g = 0; g < 4; g++) {
                const uint32_t rb = (uint32_t)(((wn * 64 + g * 16 + b_row) * ASTR + ks * 16 + b_col) * 2);
                uint32_t bH[4], bL[4];
                ldm_x4(bH, stg + 2 * ATILE_B + rb);
                ldm_x4(bL, stg + 2 * ATILE_B + TILE80 + rb);
                mma16816(acc[2 * g + 0], aH, bH);
                mma16816(acc[2 * g + 1], aH, bH + 2);
                mma16816(acc[2 * g + 0], aH, bL);
                mma16816(acc[2 * g + 1], aH, bL + 2);
                mma16816(acc[2 * g + 0], aL, bH);
                mma16816(acc[2 * g + 1], aL, bH + 2);
            }
        }
    }

    const int crow = by * 64 + wm * 16 + (lane >> 2);
    const int ccol = bx * BN + wn * 64 + (lane & 3) * 2;
    #pragma unroll
    for (int nt = 0; nt < 8; nt++) {
        const int gn = ccol + nt * 8;
        const float2 bv = *(const float2*)(bias + gn);
        float2 o0, o1;
        o0.x = acc[nt][0] + bv.x;
        o0.y = acc[nt][1] + bv.y;
        o1.x = acc[nt][2] + bv.x;
        o1.y = acc[nt][3] + bv.y;
        *(float2*)(C + (size_t)crow * DD + gn)       = o0;
        *(float2*)(C + (size_t)(crow + 8) * DD + gn) = o1;
    }
}

// ---------------------------------------------------------------------------
// fp32 -> (hi, lo) bf16 split (plain)
// ---------------------------------------------------------------------------
__global__ void split_kernel(const float* __restrict__ in,
                             __nv_bfloat16* __restrict__ hi,
                             __nv_bfloat16* __restrict__ lo, int n4)
{
    for (int i = blockIdx.x * blockDim.x + threadIdx.x; i < n4; i += gridDim.x * blockDim.x) {
        const float4 v = ((const float4*)in)[i];
        __nv_bfloat16 hx = __float2bfloat16_rn(v.x);
        __nv_bfloat16 hy = __float2bfloat16_rn(v.y);
        __nv_bfloat16 hz = __float2bfloat16_rn(v.z);
        __nv_bfloat16 hw = __float2bfloat16_rn(v.w);
        __nv_bfloat162* h2 = (__nv_bfloat162*)hi;
        __nv_bfloat162* l2 = (__nv_bfloat162*)lo;
        h2[2 * i + 0] = __nv_bfloat162(hx, hy);
        h2[2 * i + 1] = __nv_bfloat162(hz, hw);
        l2[2 * i + 0] = __nv_bfloat162(__float2bfloat16_rn(v.x - __bfloat162float(hx)),
                                       __float2bfloat16_rn(v.y - __bfloat162float(hy)));
        l2[2 * i + 1] = __nv_bfloat162(__float2bfloat16_rn(v.z - __bfloat162float(hz)),
                                       __float2bfloat16_rn(v.w - __bfloat162float(hw)));
    }
}

// ---------------------------------------------------------------------------
// transposing split: Wu (fp32) -> Wu^T hi/lo (bf16), one pass
// ---------------------------------------------------------------------------
__global__ void split_t_kernel(const float* __restrict__ in,
                               __nv_bfloat16* __restrict__ hi,
                               __nv_bfloat16* __restrict__ lo)
{
    __shared__ float t[32][33];
    const int x  = blockIdx.x * 32 + threadIdx.x;
    const int y0 = blockIdx.y * 32 + threadIdx.y;
    #pragma unroll
    for (int j = 0; j < 4; j++)
        t[threadIdx.y + j * 8][threadIdx.x] = in[(size_t)(y0 + j * 8) * DD + x];
    __syncthreads();
    const int x2 = blockIdx.y * 32 + threadIdx.x;
    const int y2 = blockIdx.x * 32 + threadIdx.y;
    #pragma unroll
    for (int j = 0; j < 4; j++) {
        const float v = t[threadIdx.x][threadIdx.y + j * 8];
        const __nv_bfloat16 h = __float2bfloat16_rn(v);
        hi[(size_t)(y2 + j * 8) * DD + x2] = h;
        lo[(size_t)(y2 + j * 8) * DD + x2] = __float2bfloat16_rn(v - __bfloat162float(h));
    }
}

// ---------------------------------------------------------------------------
// c[e] = sum_d Wf[e,d] * bu[d]
// ---------------------------------------------------------------------------
__global__ void bias_proj(const float* __restrict__ Wf,
                          const float* __restrict__ bu,
                          float* __restrict__ c)
{
    __shared__ float red[8];
    const int e = blockIdx.x;
    float s = 0.0f;
    for (int d = threadIdx.x; d < DD; d += 256)
        s += Wf[(size_t)e * DD + d] * bu[d];
    #pragma unroll
    for (int o = 16; o > 0; o >>= 1)
        s += __shfl_down_sync(0xffffffffu, s, o);
    if ((threadIdx.x & 31) == 0) red[threadIdx.x >> 5] = s;
    __syncthreads();
    if (threadIdx.x == 0) {
        float t = 0.0f;
        #pragma unroll
        for (int w = 0; w < 8; w++) t += red[w];
        c[e] = t;
    }
}

// ---------------------------------------------------------------------------
// Per-(b,chunk) prefix products of a_t within chunk: P[b*SS + ch*CHS + s]
// ---------------------------------------------------------------------------
__global__ void prefix_kernel(const float* __restrict__ mask,
                              const float* __restrict__ decay_p,
                              float* __restrict__ P)
{
    const int g = threadIdx.x;          // 0..255
    if (g >= BB * NCH) return;
    const int b  = g >> 5;
    const int ch = g & 31;
    const float decay = get_decay(decay_p);
    const float* mrow = mask + (size_t)b * SS + ch * CHS;
    float* prow = P + (size_t)b * SS + ch * CHS;
    float A = 1.0f;
    for (int s = 0; s < CHS; s++) {
        const float m = mrow[s];
        A *= m * decay + (1.0f - m);
        prow[s] = A;
    }
}

// ---------------------------------------------------------------------------
// combine: chain chunk summaries per (b,d). A_ch = P at chunk end.
// ---------------------------------------------------------------------------
__global__ void scan_combine(const float* __restrict__ P,
                             const float* __restrict__ Be,
                             float* __restrict__ cin)
{
    const int g = blockIdx.x * blockDim.x + threadIdx.x;   // 0..8191 = b*DD+d
    const int b = g >> 10;
    float carry = 0.0f;
    #pragma unroll
    for (int ch = 0; ch < NCH; ch++) {
        cin[ch * NCD + g] = carry;
        const float A = P[(size_t)b * SS + ch * CHS + (CHS - 1)];
        carry = fmaf(A, carry, Be[ch * NCD + g]);
    }
}

// ---------------------------------------------------------------------------
// finish (fully parallel streaming): out = yscan + P_t * cin + bf
// ---------------------------------------------------------------------------
__global__ void scan_finish(const float* __restrict__ Y,
                            const float* __restrict__ P,
                            const float* __restrict__ cin,
                            const float* __restrict__ bf,
                            float* __restrict__ out)
{
    const int n4 = MTOT * DD / 4;
    for (int i = blockIdx.x * blockDim.x + threadIdx.x; i < n4; i += gridDim.x * blockDim.x) {
        const int m  = i >> 8;            // row (b*SS + s)
        const int d  = (i & 255) * 4;
        const int b  = m >> 12;
        const int s  = m & (SS - 1);
        const int ch = s >> 7;
        const float p = P[(size_t)b * SS + s];
        const float4 yv = *(const float4*)(Y + (size_t)m * DD + d);
        const float4 cv = *(const float4*)(cin + ch * NCD + b * DD + d);
        const float4 bv = *(const float4*)(bf + d);
        float4 o;
        o.x = fmaf(p, cv.x, yv.x) + bv.x;
        o.y = fmaf(p, cv.y, yv.y) + bv.y;
        o.z = fmaf(p, cv.z, yv.z) + bv.z;
        o.w = fmaf(p, cv.w, yv.w) + bv.w;
        *(float4*)(out + (size_t)m * DD + d) = o;
    }
}

// ---------------------------------------------------------------------------
// kernel_launch
// Inputs: 0:x (B,S,D)  1:mask (B,S)  2:Wu (D,D)  3:bu (D)
//         4:Wf (D,D)   5:bf (D)      6:decay_param (1)
//
// Math: out = scan(m*(x*Wu^T + bu))*Wf^T + bf == scan(m*(x*W2^T + c)) + bf
//       with W2 = Wf*Wu, c = Wf*bu. Chunked scan:
//       mem_t = scan0_t + P_t*cin (within-chunk scan in the GEMM epilogue).
// ---------------------------------------------------------------------------
extern "C" void kernel_launch(void* const* d_in, const int* in_sizes, int n_in,
                              void* d_out, int out_size)
{
    const float* x     = (const float*)d_in[0];
    const float* mask  = (const float*)d_in[1];
    const float* Wu    = (const float*)d_in[2];
    const float* bu    = (const float*)d_in[3];
    const float* Wf    = (const float*)d_in[4];
    const float* bf    = (const float*)d_in[5];
    const float* decay = (const float*)d_in[6];
    float* out = (float*)d_out;

    float *y, *w2, *cvec, *zero, *P, *Be, *cin;
    __nv_bfloat16 *wuthi, *wutlo, *wfhi, *wflo, *w2hi, *w2lo;
    cudaGetSymbolAddress((void**)&y,     g_y);
    cudaGetSymbolAddress((void**)&w2,    g_w2);
    cudaGetSymbolAddress((void**)&wuthi, g_wuthi);
    cudaGetSymbolAddress((void**)&wutlo, g_wutlo);
    cudaGetSymbolAddress((void**)&wfhi,  g_wfhi);
    cudaGetSymbolAddress((void**)&wflo,  g_wflo);
    cudaGetSymbolAddress((void**)&w2hi,  g_w2hi);
    cudaGetSymbolAddress((void**)&w2lo,  g_w2lo);
    cudaGetSymbolAddress((void**)&cvec,  g_c);
    cudaGetSymbolAddress((void**)&zero,  g_zero);
    cudaGetSymbolAddress((void**)&P,     g_P);
    cudaGetSymbolAddress((void**)&Be,    g_Be);
    cudaGetSymbolAddress((void**)&cin,   g_cin);

    cudaFuncSetAttribute(gemm_xf32, cudaFuncAttributeMaxDynamicSharedMemorySize, FUSED_SMEM);
    cudaFuncSetAttribute(gemm_w2,   cudaFuncAttributeMaxDynamicSharedMemorySize, SM1_SMEM);

    // --- weight prep + prefix products (small) ---
    split_t_kernel<<<dim3(32, 32), dim3(32, 8)>>>(Wu, wuthi, wutlo);   // Wu^T hi/lo
    split_kernel<<<128, 256>>>(Wf, wfhi, wflo, DD * DD / 4);
    bias_proj<<<DD, 256>>>(Wf, bu, cvec);                              // c = Wf*bu
    prefix_kernel<<<1, 256>>>(mask, decay, P);

    // W2 = Wf * Wu
    gemm_w2<<<dim3(DD / BN, 1024 / 64), 256, SM1_SMEM>>>(
        wfhi, wflo, wuthi, wutlo, zero, w2);
    split_kernel<<<128, 256>>>(w2, w2hi, w2lo, DD * DD / 4);

    // --- big path: y = x*W2^T + c, within-chunk scan fused in epilogue ---
    gemm_xf32<<<dim3(DD / BN, MTOT / 128), 256, FUSED_SMEM>>>(
        x, w2hi, w2lo, cvec, mask, decay, y, Be);

    // chunk combine + fully-parallel finish
    scan_combine<<<NCD / 256, 256>>>(P, Be, cin);
    scan_finish<<<4096, 256>>>(y, P, cin, bf, out);
}